// round 11
// baseline (speedup 1.0000x reference)
#include <cuda_runtime.h>
#include <math.h>

#define B_ 32
#define S_ 128
#define V_ 32000
#define NB 148
#define NT 768
#define NW 24
#define USTRIDE 36
#define SMEM_BYTES (1024*USTRIDE*4)   // 147456; S9 B-frags need 128KB

typedef unsigned long long u64;

// ---------------- scratch ----------------
__device__ __align__(16) float g_gruP[16*3072*32];    // [mat*8+kc2][row][b]
__device__ __align__(16) float g_decT[1024*32];       // [h][b]
__device__ __align__(16) float g_vP[32*1024*32];      // [kc][e][b]
__device__ __align__(16) float g_v[32*1024];          // [b][e]
__device__ __align__(16) float g_scores[32*128];
__device__ __align__(16) float g_attw[32*128];
__device__ __align__(16) float g_ctx[1024*32];        // [e][b]
__device__ __align__(16) float g_combP[32*1024*32];   // [kc2][i][b]
__device__ __align__(16) float g_outU[1024*32];       // [k][b]
__device__ __align__(16) float g_logits[32*32000];    // [b][v]  (kh=0 partial, then combined)
__device__ __align__(16) float g_logits2[32*32000];   // [b][v]  (kh=1 partial)
__device__ float g_ps[256];

// ---------------- grid barrier ----------------
__device__ unsigned g_bar_cnt;
__device__ volatile unsigned g_bar_gen;

__device__ __forceinline__ void gsync(){
    __syncthreads();
    if (threadIdx.x == 0){
        unsigned target = g_bar_gen + 1u;
        __threadfence();
        if (atomicAdd(&g_bar_cnt, 1u) == NB - 1u){
            g_bar_cnt = 0u;
            __threadfence();
            g_bar_gen = target;
        } else {
            while ((int)(g_bar_gen - target) < 0) __nanosleep(64);
            __threadfence();
        }
    }
    __syncthreads();
}

// ---------------- helpers ----------------
#define FMA2(acc,a,b) asm("fma.rn.f32x2 %0, %1, %2, %0;" : "+l"(acc) : "l"(a), "l"(b))
__device__ __forceinline__ u64 dup2(float w){ u64 r; asm("mov.b64 %0, {%1, %1};" : "=l"(r) : "f"(w)); return r; }
__device__ __forceinline__ u64 d2u(double d){ return (u64)__double_as_longlong(d); }
__device__ __forceinline__ void unpk(u64 v, float& a, float& b){ asm("mov.b64 {%0,%1}, %2;" : "=f"(a), "=f"(b) : "l"(v)); }

// split fp32 -> bf16 hi (truncate) pair + bf16 lo (rounded residual) pair; low half = first elem
__device__ __forceinline__ void split2(float w0, float w1, unsigned& h2, unsigned& l2){
    unsigned u0 = __float_as_uint(w0), u1 = __float_as_uint(w1);
    h2 = __byte_perm(u0, u1, 0x7632);
    float l0 = w0 - __uint_as_float(u0 & 0xFFFF0000u);
    float l1 = w1 - __uint_as_float(u1 & 0xFFFF0000u);
    asm("cvt.rn.bf16x2.f32 %0, %1, %2;" : "=r"(l2) : "f"(l1), "f"(l0));
}

// m16n8k16 bf16 mma, f32 accumulate (base-arch, sm_80+)
#define MMA16816(c, a, b0r, b1r) \
    asm volatile("mma.sync.aligned.m16n8k16.row.col.f32.bf16.bf16.f32 " \
        "{%0,%1,%2,%3}, {%4,%5,%6,%7}, {%8,%9}, {%0,%1,%2,%3};" \
        : "+f"((c)[0]), "+f"((c)[1]), "+f"((c)[2]), "+f"((c)[3]) \
        : "r"((a)[0]), "r"((a)[1]), "r"((a)[2]), "r"((a)[3]), "r"(b0r), "r"(b1r))

// 12-MMA step: hi*hi + lo*hi + hi*lo for 4 n-tiles
__device__ __forceinline__ void mma12(float acc[4][4], const unsigned ah[4], const unsigned al[4],
                                      const uint4* Bs, int ksg, int lane){
    uint4 bh0 = Bs[(ksg*4+0)*32 + lane];
    uint4 bh1 = Bs[(ksg*4+1)*32 + lane];
    MMA16816(acc[0], ah, bh0.x, bh1.x);
    MMA16816(acc[0], al, bh0.x, bh1.x);
    MMA16816(acc[1], ah, bh0.y, bh1.y);
    MMA16816(acc[1], al, bh0.y, bh1.y);
    MMA16816(acc[2], ah, bh0.z, bh1.z);
    MMA16816(acc[2], al, bh0.z, bh1.z);
    MMA16816(acc[3], ah, bh0.w, bh1.w);
    MMA16816(acc[3], al, bh0.w, bh1.w);
    uint4 bl0 = Bs[(ksg*4+2)*32 + lane];
    uint4 bl1 = Bs[(ksg*4+3)*32 + lane];
    MMA16816(acc[0], ah, bl0.x, bl1.x);
    MMA16816(acc[1], ah, bl0.y, bl1.y);
    MMA16816(acc[2], ah, bl0.z, bl1.z);
    MMA16816(acc[3], ah, bl0.w, bl1.w);
}

// ================= fused kernel =================
__global__ void __launch_bounds__(NT, 1) k_fused(
    const float* __restrict__ x, const float* __restrict__ enc,
    const float* __restrict__ hid,
    const float* __restrict__ Wih, const float* __restrict__ Whh,
    const float* __restrict__ bih, const float* __restrict__ bhh,
    const float* __restrict__ Wattn,
    const float* __restrict__ Wcomb, const float* __restrict__ bcomb,
    const float* __restrict__ Wout, const float* __restrict__ bout,
    float* __restrict__ out)
{
    extern __shared__ float smU[];
    uint4* Bs = (uint4*)smU;
    const int bid = blockIdx.x, tid = threadIdx.x;
    const int wid = tid >> 5, lane = tid & 31;
    const int gws = wid * NB + bid;          // balanced warp unit id (0..3551)
    const int rf = lane >> 2, cf = (lane & 3) * 2;   // mma fragment row/col

    // ---- S0: GRU gemms via MMA (128 blocks: mat x kc4(256k) x vb(192 rows)) ----
    if (bid < 128){
        int mat = bid >> 6, r = bid & 63;
        int kc4 = r >> 4, vb = r & 15;
        const float* W   = mat ? Whh : Wih;
        const float* src = mat ? hid : x;    // [32][1024] b-major
        int k0 = kc4 * 256;
        // stage B fragments (16 k16-steps, hi/lo)
        for (int idx = tid; idx < 1024; idx += NT){
            int l = idx & 31, rest = idx >> 5;
            int ks = rest >> 1, reg = rest & 1;
            int kb = k0 + ks*16 + (l&3)*2 + reg*8;
            int nb = l >> 2;
            uint4 hv, lv; unsigned h, lo;
            split2(src[nb*1024+kb],      src[nb*1024+kb+1],      h, lo); hv.x=h; lv.x=lo;
            split2(src[(nb+8)*1024+kb],  src[(nb+8)*1024+kb+1],  h, lo); hv.y=h; lv.y=lo;
            split2(src[(nb+16)*1024+kb], src[(nb+16)*1024+kb+1], h, lo); hv.z=h; lv.z=lo;
            split2(src[(nb+24)*1024+kb], src[(nb+24)*1024+kb+1], h, lo); hv.w=h; lv.w=lo;
            Bs[(ks*4 + reg)*32 + l]     = hv;
            Bs[(ks*4 + 2 + reg)*32 + l] = lv;
        }
        __syncthreads();
        {
            int rowblk = wid >> 1, kh = wid & 1;   // 12 rowblks x 2 khalves = 24 warps
            int v0 = vb*192 + rowblk*16;
            const float* p0 = W + (size_t)(v0+rf)*1024   + k0 + kh*128 + cf;
            const float* p1 = W + (size_t)(v0+rf+8)*1024 + k0 + kh*128 + cf;
            float acc[4][4];
            #pragma unroll
            for (int nt = 0; nt < 4; nt++){ acc[nt][0]=0; acc[nt][1]=0; acc[nt][2]=0; acc[nt][3]=0; }
            float2 fA[2][4];
            #pragma unroll
            for (int s = 0; s < 2; s++){
                fA[s][0] = *(const float2*)(p0 + s*16);
                fA[s][1] = *(const float2*)(p1 + s*16);
                fA[s][2] = *(const float2*)(p0 + s*16 + 8);
                fA[s][3] = *(const float2*)(p1 + s*16 + 8);
            }
            #pragma unroll
            for (int ks2 = 0; ks2 < 8; ks2++){
                int sl = ks2 & 1;
                float2 g0=fA[sl][0], g1=fA[sl][1], g2=fA[sl][2], g3=fA[sl][3];
                if (ks2 + 2 < 8){
                    const float* q0 = p0 + (ks2+2)*16;
                    const float* q1 = p1 + (ks2+2)*16;
                    fA[sl][0]=*(const float2*)(q0); fA[sl][1]=*(const float2*)(q1);
                    fA[sl][2]=*(const float2*)(q0+8); fA[sl][3]=*(const float2*)(q1+8);
                }
                unsigned ah[4], al[4];
                split2(g0.x,g0.y,ah[0],al[0]); split2(g1.x,g1.y,ah[1],al[1]);
                split2(g2.x,g2.y,ah[2],al[2]); split2(g3.x,g3.y,ah[3],al[3]);
                mma12(acc, ah, al, Bs, kh*8 + ks2, lane);
            }
            float* P = g_gruP + (size_t)(mat*8 + kc4*2 + kh)*3072*32;
            #pragma unroll
            for (int nt = 0; nt < 4; nt++){
                int jb = nt*8 + cf;
                *(float2*)(P + (size_t)(v0+rf)*32   + jb) = make_float2(acc[nt][0], acc[nt][1]);
                *(float2*)(P + (size_t)(v0+rf+8)*32 + jb) = make_float2(acc[nt][2], acc[nt][3]);
            }
        }
    }
    gsync();

    // ---- S1: GRU activation -> decT[h][b] (warp per h) ----
    for (int u = gws; u < 1024; u += NB*NW){
        int h = u, b = lane;
        float s0=0,s1=0,s2=0,s3=0,s4=0,s5=0;
        #pragma unroll
        for (int kc = 0; kc < 8; kc++){
            const float* Pa = g_gruP + (size_t)kc*3072*32;
            const float* Pb = g_gruP + (size_t)(8+kc)*3072*32;
            s0 += Pa[(size_t)h*32+b];
            s1 += Pa[(size_t)(1024+h)*32+b];
            s2 += Pa[(size_t)(2048+h)*32+b];
            s3 += Pb[(size_t)h*32+b];
            s4 += Pb[(size_t)(1024+h)*32+b];
            s5 += Pb[(size_t)(2048+h)*32+b];
        }
        float xr=s0+bih[h], xz=s1+bih[1024+h], xn=s2+bih[2048+h];
        float hr=s3+bhh[h], hz=s4+bhh[1024+h], hn=s5+bhh[2048+h];
        float rr = 1.0f/(1.0f+expf(-(xr+hr)));
        float zz = 1.0f/(1.0f+expf(-(xz+hz)));
        float nn = tanhf(xn + rr*hn);
        g_decT[h*32+b] = (1.0f-zz)*nn + zz*hid[b*1024+h];
    }
    gsync();

    // ---- S2: v gemm partials (FFMA2; W e-contiguous = coalesced) ----
    if (bid < 128){
        int kc = bid >> 2, e0 = (bid & 3) * 256;
        int k0 = kc * 32;
        for (int idx = tid; idx < 1024; idx += NT){
            int k = idx >> 5, b = idx & 31;
            smU[k*USTRIDE + b] = g_decT[(k0+k)*32 + b];
        }
        __syncthreads();
        if (tid < 256){
            int e = e0 + tid;
            const float* wp = Wattn + (size_t)k0*2048 + 1024 + e;
            u64 acc[16];
            #pragma unroll
            for (int p = 0; p < 16; p++) acc[p] = 0;
            #pragma unroll 8
            for (int k = 0; k < 32; k++){
                u64 wd = dup2(wp[(size_t)k*2048]);
                #pragma unroll
                for (int p = 0; p < 16; p += 2){
                    double2 u2 = *(const double2*)(smU + k*USTRIDE + 2*p);
                    FMA2(acc[p],   wd, d2u(u2.x));
                    FMA2(acc[p+1], wd, d2u(u2.y));
                }
            }
            float* o = g_vP + ((size_t)kc*1024 + e)*32;
            #pragma unroll
            for (int p = 0; p < 16; p++){
                float lo, hi; unpk(acc[p], lo, hi);
                *(float2*)(o + 2*p) = make_float2(lo, hi);
            }
        }
    }
    gsync();

    // ---- S3: v reduce -> g_v[b][e] (warp per e) ----
    for (int u = gws; u < 1024; u += NB*NW){
        int e = u, b = lane;
        float s = 0.0f;
        #pragma unroll
        for (int kc = 0; kc < 32; kc++) s += g_vP[((size_t)kc*1024 + e)*32 + b];
        g_v[b*1024 + e] = s;
    }
    gsync();

    // ---- S4: scores ----
    for (int u = gws; u < 4096; u += NB*NW){
        int b = u & 31, s = u >> 5;
        const float4* ep = (const float4*)(enc + (size_t)(s*32+b)*1024);
        const float4* vp = (const float4*)(g_v + b*1024);
        float a = 0.0f;
        #pragma unroll
        for (int i = 0; i < 8; i++){
            float4 e4 = ep[i*32 + lane];
            float4 v4 = vp[i*32 + lane];
            a += e4.x*v4.x + e4.y*v4.y + e4.z*v4.z + e4.w*v4.w;
        }
        #pragma unroll
        for (int o = 16; o; o >>= 1) a += __shfl_xor_sync(0xFFFFFFFFu, a, o);
        if (lane == 0) g_scores[b*128 + s] = a;
    }
    gsync();

    // ---- S5: softmax + attn weights out ----
    if (gws < 32){
        int b = gws;
        float v0 = g_scores[b*128 + lane];
        float v1 = g_scores[b*128 + 32 + lane];
        float v2 = g_scores[b*128 + 64 + lane];
        float v3 = g_scores[b*128 + 96 + lane];
        float m = fmaxf(fmaxf(v0,v1), fmaxf(v2,v3));
        #pragma unroll
        for (int o = 16; o; o >>= 1) m = fmaxf(m, __shfl_xor_sync(0xFFFFFFFFu, m, o));
        float e0 = expf(v0-m), e1 = expf(v1-m), e2 = expf(v2-m), e3 = expf(v3-m);
        float s = e0+e1+e2+e3;
        #pragma unroll
        for (int o = 16; o; o >>= 1) s += __shfl_xor_sync(0xFFFFFFFFu, s, o);
        float inv = 1.0f / s;
        float w0 = e0*inv, w1 = e1*inv, w2 = e2*inv, w3 = e3*inv;
        g_attw[b*128 + lane]      = w0;  out[(size_t)B_*V_ + b*128 + lane]      = w0;
        g_attw[b*128 + 32 + lane] = w1;  out[(size_t)B_*V_ + b*128 + 32 + lane] = w1;
        g_attw[b*128 + 64 + lane] = w2;  out[(size_t)B_*V_ + b*128 + 64 + lane] = w2;
        g_attw[b*128 + 96 + lane] = w3;  out[(size_t)B_*V_ + b*128 + 96 + lane] = w3;
    }
    gsync();

    // ---- S6: context (warp = (b, e-chunk of 32)) ----
    for (int u = gws; u < 1024; u += NB*NW){
        int b = u >> 5, e = (u & 31)*32 + lane;
        const float* ep = enc + (size_t)b*1024 + e;
        const float* wsp = g_attw + b*128;
        float a = 0.0f;
        #pragma unroll 16
        for (int s = 0; s < 128; s++) a += wsp[s] * ep[(size_t)s*32768];
        g_ctx[e*32 + b] = a;
    }
    gsync();

    // ---- S7: comb gemm via MMA (128 blocks: kc(128k) x rc(128 rows)) ----
    if (bid < 128){
        int kc = bid >> 3, rc = bid & 7;
        int k0 = kc * 128;
        for (int idx = tid; idx < 512; idx += NT){
            int l = idx & 31, rest = idx >> 5;
            int ks = rest >> 1, reg = rest & 1;
            int kb = k0 + ks*16 + (l&3)*2 + reg*8;
            int nb = l >> 2;
            uint4 hv, lv; unsigned h, lo;
            if (kc < 8){
                split2(x[nb*1024+kb],      x[nb*1024+kb+1],      h, lo); hv.x=h; lv.x=lo;
                split2(x[(nb+8)*1024+kb],  x[(nb+8)*1024+kb+1],  h, lo); hv.y=h; lv.y=lo;
                split2(x[(nb+16)*1024+kb], x[(nb+16)*1024+kb+1], h, lo); hv.z=h; lv.z=lo;
                split2(x[(nb+24)*1024+kb], x[(nb+24)*1024+kb+1], h, lo); hv.w=h; lv.w=lo;
            } else {
                int kk = kb - 1024;
                split2(g_ctx[kk*32+nb],      g_ctx[(kk+1)*32+nb],      h, lo); hv.x=h; lv.x=lo;
                split2(g_ctx[kk*32+nb+8],    g_ctx[(kk+1)*32+nb+8],    h, lo); hv.y=h; lv.y=lo;
                split2(g_ctx[kk*32+nb+16],   g_ctx[(kk+1)*32+nb+16],   h, lo); hv.z=h; lv.z=lo;
                split2(g_ctx[kk*32+nb+24],   g_ctx[(kk+1)*32+nb+24],   h, lo); hv.w=h; lv.w=lo;
            }
            Bs[(ks*4 + reg)*32 + l]     = hv;
            Bs[(ks*4 + 2 + reg)*32 + l] = lv;
        }
        __syncthreads();
        if (wid < 16){
            int rowblk = wid >> 1, kh = wid & 1;   // 8 rowblks x 2 khalves (64k each)
            int v0 = rc*128 + rowblk*16;
            const float* p0 = Wcomb + (size_t)(v0+rf)*2048   + k0 + kh*64 + cf;
            const float* p1 = Wcomb + (size_t)(v0+rf+8)*2048 + k0 + kh*64 + cf;
            float acc[4][4];
            #pragma unroll
            for (int nt = 0; nt < 4; nt++){ acc[nt][0]=0; acc[nt][1]=0; acc[nt][2]=0; acc[nt][3]=0; }
            #pragma unroll
            for (int ks2 = 0; ks2 < 4; ks2++){
                float2 g0 = *(const float2*)(p0 + ks2*16);
                float2 g1 = *(const float2*)(p1 + ks2*16);
                float2 g2 = *(const float2*)(p0 + ks2*16 + 8);
                float2 g3 = *(const float2*)(p1 + ks2*16 + 8);
                unsigned ah[4], al[4];
                split2(g0.x,g0.y,ah[0],al[0]); split2(g1.x,g1.y,ah[1],al[1]);
                split2(g2.x,g2.y,ah[2],al[2]); split2(g3.x,g3.y,ah[3],al[3]);
                mma12(acc, ah, al, Bs, kh*4 + ks2, lane);
            }
            float* P = g_combP + (size_t)(kc*2 + kh)*1024*32;
            #pragma unroll
            for (int nt = 0; nt < 4; nt++){
                int jb = nt*8 + cf;
                *(float2*)(P + (size_t)(v0+rf)*32   + jb) = make_float2(acc[nt][0], acc[nt][1]);
                *(float2*)(P + (size_t)(v0+rf+8)*32 + jb) = make_float2(acc[nt][2], acc[nt][3]);
            }
        }
    }
    gsync();

    // ---- S8: comb reduce + bias -> outU (warp per k) ----
    for (int u = gws; u < 1024; u += NB*NW){
        int k = u, b = lane;
        float s = bcomb[k];
        #pragma unroll
        for (int kc = 0; kc < 32; kc++) s += g_combP[((size_t)kc*1024 + k)*32 + b];
        g_outU[k*32 + b] = s;
    }
    gsync();

    // ---- S9: W_out gemm via MMA (4000 units: 16 rows x K-half 512) ----
    {
        for (int idx = tid; idx < 4096; idx += NT){
            int l = idx & 31, rest = idx >> 5;
            int ks = rest >> 1, reg = rest & 1;
            int kb = ks*16 + (l&3)*2 + reg*8;
            int nb = l >> 2;
            uint4 hv, lv; unsigned h, lo;
            split2(g_outU[kb*32 + nb],      g_outU[(kb+1)*32 + nb],      h, lo); hv.x=h; lv.x=lo;
            split2(g_outU[kb*32 + nb + 8],  g_outU[(kb+1)*32 + nb + 8],  h, lo); hv.y=h; lv.y=lo;
            split2(g_outU[kb*32 + nb + 16], g_outU[(kb+1)*32 + nb + 16], h, lo); hv.z=h; lv.z=lo;
            split2(g_outU[kb*32 + nb + 24], g_outU[(kb+1)*32 + nb + 24], h, lo); hv.w=h; lv.w=lo;
            Bs[(ks*4 + reg)*32 + l]     = hv;
            Bs[(ks*4 + 2 + reg)*32 + l] = lv;
        }
        __syncthreads();

        for (int wu = gws; wu < 4000; wu += NB*NW){
            int v0 = (wu >> 1) * 16;
            int kh = wu & 1;
            const float* p0 = Wout + (size_t)(v0+rf)*1024   + kh*512 + cf;
            const float* p1 = Wout + (size_t)(v0+rf+8)*1024 + kh*512 + cf;
            float acc[4][4];
            #pragma unroll
            for (int nt = 0; nt < 4; nt++){ acc[nt][0]=0; acc[nt][1]=0; acc[nt][2]=0; acc[nt][3]=0; }
            float2 fA[2][4];
            #pragma unroll
            for (int s = 0; s < 2; s++){
                fA[s][0] = *(const float2*)(p0 + s*16);
                fA[s][1] = *(const float2*)(p1 + s*16);
                fA[s][2] = *(const float2*)(p0 + s*16 + 8);
                fA[s][3] = *(const float2*)(p1 + s*16 + 8);
            }
            #pragma unroll 4
            for (int ks2 = 0; ks2 < 32; ks2++){
                int sl = ks2 & 1;
                float2 g0=fA[sl][0], g1=fA[sl][1], g2=fA[sl][2], g3=fA[sl][3];
                if (ks2 + 2 < 32){
                    const float* q0 = p0 + (ks2+2)*16;
                    const float* q1 = p1 + (ks2+2)*16;
                    fA[sl][0]=*(const float2*)(q0); fA[sl][1]=*(const float2*)(q1);
                    fA[sl][2]=*(const float2*)(q0+8); fA[sl][3]=*(const float2*)(q1+8);
                }
                unsigned ah[4], al[4];
                split2(g0.x,g0.y,ah[0],al[0]); split2(g1.x,g1.y,ah[1],al[1]);
                split2(g2.x,g2.y,ah[2],al[2]); split2(g3.x,g3.y,ah[3],al[3]);
                mma12(acc, ah, al, Bs, kh*32 + ks2, lane);
            }
            float* P = kh ? g_logits2 : g_logits;
            float bb0 = kh ? 0.0f : bout[v0 + rf];
            float bb1 = kh ? 0.0f : bout[v0 + rf + 8];
            #pragma unroll
            for (int nt = 0; nt < 4; nt++){
                int jg = nt*8 + cf;
                P[(size_t)jg*V_     + v0 + rf]     = acc[nt][0] + bb0;
                P[(size_t)(jg+1)*V_ + v0 + rf]     = acc[nt][1] + bb0;
                P[(size_t)jg*V_     + v0 + rf + 8] = acc[nt][2] + bb1;
                P[(size_t)(jg+1)*V_ + v0 + rf + 8] = acc[nt][3] + bb1;
            }
        }
    }
    gsync();

    // ---- S10: combine k-halves + log-softmax partial sums (logits bounded; no max) ----
    if (gws < 256){
        int b = gws >> 3, c = gws & 7;
        float* pa = g_logits + (size_t)b*V_ + c*4000;
        const float* pb = g_logits2 + (size_t)b*V_ + c*4000;
        float s0 = 0.0f, s1 = 0.0f;
        #pragma unroll 2
        for (int j = 0; j < 62; j++){
            float va = pa[j*32 + lane] + pb[j*32 + lane];
            pa[j*32 + lane] = va;
            s0 += expf(va);
            float vb = pa[(j+62)*32 + lane] + pb[(j+62)*32 + lane];
            pa[(j+62)*32 + lane] = vb;
            s1 += expf(vb);
        }
        {
            float va = pa[124*32 + lane] + pb[124*32 + lane];
            pa[124*32 + lane] = va;
            s0 += expf(va);
        }
        float s = s0 + s1;
        #pragma unroll
        for (int o = 16; o; o >>= 1) s += __shfl_xor_sync(0xFFFFFFFFu, s, o);
        if (lane == 0) g_ps[gws] = s;
    }
    gsync();

    // ---- S11+S12: per-block combine (redundant) + final write ----
    if (tid < 32){
        float S = 0.0f;
        #pragma unroll
        for (int c = 0; c < 8; c++) S += g_ps[tid*8 + c];
        smU[tid] = logf(S);
    }
    __syncthreads();
    for (int u = bid*NT + tid; u < 256000; u += NB*NT){
        int b = u / 8000, r = u - b*8000;
        float4 a = ((const float4*)(g_logits + (size_t)b*V_))[r];
        float off = smU[b];
        ((float4*)(out + (size_t)b*V_))[r] =
            make_float4(a.x-off, a.y-off, a.z-off, a.w-off);
    }
}

// ---------------- launch ----------------
extern "C" void kernel_launch(void* const* d_in, const int* in_sizes, int n_in,
                              void* d_out, int out_size)
{
    const float* x     = (const float*)d_in[0];
    const float* enc   = (const float*)d_in[1];
    const float* hid   = (const float*)d_in[2];
    const float* Wih   = (const float*)d_in[3];
    const float* Whh   = (const float*)d_in[4];
    const float* bih   = (const float*)d_in[5];
    const float* bhh   = (const float*)d_in[6];
    const float* Wattn = (const float*)d_in[7];
    // d_in[8] = b_attn: softmax-invariant, unused
    const float* Wcomb = (const float*)d_in[9];
    const float* bcomb = (const float*)d_in[10];
    const float* Wout  = (const float*)d_in[11];
    const float* bout  = (const float*)d_in[12];
    float* out = (float*)d_out;

    static bool once = false;
    if (!once){
        cudaFuncSetAttribute(k_fused, cudaFuncAttributeMaxDynamicSharedMemorySize, SMEM_BYTES);
        once = true;
    }
    k_fused<<<NB, NT, SMEM_BYTES>>>(x, enc, hid, Wih, Whh, bih, bhh,
                                    Wattn, Wcomb, bcomb, Wout, bout, out);
}

// round 12
// speedup vs baseline: 1.1147x; 1.1147x over previous
#include <cuda_runtime.h>
#include <math.h>

#define B_ 32
#define S_ 128
#define V_ 32000
#define NB 148
#define NT 512
#define USTRIDE 36
#define SMU_FLOATS (1024*USTRIDE)
#define SMT_WARP   (2*16*34)
#define SMEM_BYTES ((SMU_FLOATS + 16*SMT_WARP)*4)   // 217088

typedef unsigned long long u64;

// ---------------- scratch ----------------
__device__ __align__(16) float g_gx[3072*32];         // x-gate accumulator [row][b]
__device__ __align__(16) float g_gh[3072*32];         // h-gate accumulator [row][b]
__device__ __align__(16) float g_decT[1024*32];       // [h][b]
__device__ __align__(16) float g_v[32*1024];          // [b][e] (atomic-accumulated)
__device__ __align__(16) float g_scores[32*128];
__device__ __align__(16) float g_attw[32*128];
__device__ __align__(16) float g_ctx[1024*32];        // [e][b]
__device__ __align__(16) float g_outU[1024*32];       // [k][b] (init=bcomb, atomic-accumulated)
__device__ __align__(16) float g_logits[32*32000];    // [b][v]
__device__ float g_ps[256];

// ---------------- grid barrier ----------------
__device__ unsigned g_bar_cnt;
__device__ volatile unsigned g_bar_gen;

__device__ __forceinline__ void gsync(){
    __syncthreads();
    if (threadIdx.x == 0){
        unsigned target = g_bar_gen + 1u;
        __threadfence();
        if (atomicAdd(&g_bar_cnt, 1u) == NB - 1u){
            g_bar_cnt = 0u;
            __threadfence();
            g_bar_gen = target;
        } else {
            while ((int)(g_bar_gen - target) < 0) __nanosleep(64);
            __threadfence();
        }
    }
    __syncthreads();
}

// ---------------- f32x2 helpers ----------------
#define FMA2(acc,a,b) asm("fma.rn.f32x2 %0, %1, %2, %0;" : "+l"(acc) : "l"(a), "l"(b))
__device__ __forceinline__ u64 dup2(float w){ u64 r; asm("mov.b64 %0, {%1, %1};" : "=l"(r) : "f"(w)); return r; }
__device__ __forceinline__ u64 d2u(double d){ return (u64)__double_as_longlong(d); }
__device__ __forceinline__ void unpk(u64 v, float& a, float& b){ asm("mov.b64 {%0,%1}, %2;" : "=f"(a), "=f"(b) : "l"(v)); }

__device__ __forceinline__ void rb_k(float w0, float w1, float w2, float w3,
                                     const float* Ub, u64 acc[16]){
    double2 ua = *(const double2*)(Ub);
    double2 ub = *(const double2*)(Ub + 4);
    u64 u0 = d2u(ua.x), u1 = d2u(ua.y), u2 = d2u(ub.x), u3 = d2u(ub.y);
    u64 d0 = dup2(w0), d1 = dup2(w1), d2 = dup2(w2), d3 = dup2(w3);
    FMA2(acc[0],  d0, u0); FMA2(acc[1],  d0, u1); FMA2(acc[2],  d0, u2); FMA2(acc[3],  d0, u3);
    FMA2(acc[4],  d1, u0); FMA2(acc[5],  d1, u1); FMA2(acc[6],  d1, u2); FMA2(acc[7],  d1, u3);
    FMA2(acc[8],  d2, u0); FMA2(acc[9],  d2, u1); FMA2(acc[10], d2, u2); FMA2(acc[11], d2, u3);
    FMA2(acc[12], d3, u0); FMA2(acc[13], d3, u1); FMA2(acc[14], d3, u2); FMA2(acc[15], d3, u3);
}

__device__ __forceinline__ void rb_j(float4 c0, float4 c1, float4 c2, float4 c3,
                                     const float* Ub, u64 acc[16]){
    rb_k(c0.x, c1.x, c2.x, c3.x, Ub,             acc);
    rb_k(c0.y, c1.y, c2.y, c3.y, Ub + USTRIDE,   acc);
    rb_k(c0.z, c1.z, c2.z, c3.z, Ub + 2*USTRIDE, acc);
    rb_k(c0.w, c1.w, c2.w, c3.w, Ub + 3*USTRIDE, acc);
}

__device__ __forceinline__ void rb_stage(float* st, const u64 acc[16], int rg, int bq, int par){
    float* s = st + par*(16*34);
    #pragma unroll
    for (int i = 0; i < 4; i++){
        #pragma unroll
        for (int p = 0; p < 4; p++){
            float lo, hi; unpk(acc[i*4+p], lo, hi);
            *(float2*)(s + (rg*4+i)*34 + bq*8 + 2*p) = make_float2(lo, hi);
        }
    }
    __syncwarp();
}

// split fp32 -> bf16 hi (truncate) pair + bf16 lo (rounded residual) pair
__device__ __forceinline__ void split2(float w0, float w1, unsigned& h2, unsigned& l2){
    unsigned u0 = __float_as_uint(w0), u1 = __float_as_uint(w1);
    h2 = __byte_perm(u0, u1, 0x7632);
    float l0 = w0 - __uint_as_float(u0 & 0xFFFF0000u);
    float l1 = w1 - __uint_as_float(u1 & 0xFFFF0000u);
    asm("cvt.rn.bf16x2.f32 %0, %1, %2;" : "=r"(l2) : "f"(l1), "f"(l0));
}

// m16n8k16 bf16 mma, f32 accumulate (base-arch instruction, sm_80+)
#define MMA16816(c, a, b0r, b1r) \
    asm volatile("mma.sync.aligned.m16n8k16.row.col.f32.bf16.bf16.f32 " \
        "{%0,%1,%2,%3}, {%4,%5,%6,%7}, {%8,%9}, {%0,%1,%2,%3};" \
        : "+f"((c)[0]), "+f"((c)[1]), "+f"((c)[2]), "+f"((c)[3]) \
        : "r"((a)[0]), "r"((a)[1]), "r"((a)[2]), "r"((a)[3]), "r"(b0r), "r"(b1r))

// ================= fused kernel =================
__global__ void __launch_bounds__(NT, 1) k_fused(
    const float* __restrict__ x, const float* __restrict__ enc,
    const float* __restrict__ hid,
    const float* __restrict__ Wih, const float* __restrict__ Whh,
    const float* __restrict__ bih, const float* __restrict__ bhh,
    const float* __restrict__ Wattn,
    const float* __restrict__ Wcomb, const float* __restrict__ bcomb,
    const float* __restrict__ Wout, const float* __restrict__ bout,
    float* __restrict__ out)
{
    extern __shared__ float smU[];
    float* smT = smU + SMU_FLOATS;
    const int bid = blockIdx.x, tid = threadIdx.x;
    const int wid = tid >> 5, lane = tid & 31;
    const int gtid = bid * NT + tid;
    const int gws = wid * NB + bid;     // block-balanced warp unit id
    const int rg  = lane >> 3;
    const int bq  = (lane >> 1) & 3;
    const int par = lane & 1;
    float* stW = smT + wid * SMT_WARP;

    // ---- Sinit: zero gate accumulators, g_v; init g_outU = bcomb ----
    for (int u = gtid; u < 3072*32; u += NB*NT){ g_gx[u] = 0.0f; g_gh[u] = 0.0f; }
    for (int u = gtid; u < 32768; u += NB*NT){
        g_v[u] = 0.0f;
        g_outU[u] = bcomb[u >> 5];
    }
    gsync();

    // ---- S0: GRU gemm partials -> RED into g_gx / g_gh ----
    if (bid < 128){
        int mat = bid >> 6, r = bid & 63;
        int kc = r >> 4, vb = r & 15;
        const float* W   = mat ? Whh : Wih;
        const float* src = mat ? hid : x;
        int k0 = kc * 256;
        for (int idx = tid; idx < 256*32; idx += NT){
            int b = idx >> 8, kk = idx & 255;
            smU[kk*USTRIDE + b] = src[b*1024 + k0 + kk];
        }
        __syncthreads();
        if (wid < 12){
            int urow0 = vb*192 + wid*16;
            int row0 = urow0 + rg*4;
            const float4* w0 = (const float4*)(W + (size_t)(row0+0)*1024 + k0) + par;
            const float4* w1 = (const float4*)(W + (size_t)(row0+1)*1024 + k0) + par;
            const float4* w2 = (const float4*)(W + (size_t)(row0+2)*1024 + k0) + par;
            const float4* w3 = (const float4*)(W + (size_t)(row0+3)*1024 + k0) + par;
            u64 acc[16];
            #pragma unroll
            for (int p = 0; p < 16; p++) acc[p] = 0;
            float4 a0 = w0[0], a1 = w1[0], a2 = w2[0], a3 = w3[0];
            for (int j = 0; j < 32; j++){
                float4 c0 = a0, c1 = a1, c2 = a2, c3 = a3;
                if (j + 1 < 32){
                    a0 = w0[2*(j+1)]; a1 = w1[2*(j+1)];
                    a2 = w2[2*(j+1)]; a3 = w3[2*(j+1)];
                }
                rb_j(c0, c1, c2, c3, smU + ((2*j+par)*4)*USTRIDE + bq*8, acc);
            }
            rb_stage(stW, acc, rg, bq, par);
            float* P = mat ? g_gh : g_gx;
            #pragma unroll
            for (int r2 = 0; r2 < 16; r2++){
                float v = stW[r2*34 + lane] + stW[16*34 + r2*34 + lane];
                atomicAdd(&P[(size_t)(urow0 + r2)*32 + lane], v);
            }
            __syncwarp();
        }
    }
    gsync();

    // ---- S1: GRU activation -> decT[h][b] ----
    if (gtid < 32768){
        int h = gtid >> 5, b = gtid & 31;
        float xr = g_gx[(size_t)h*32+b]          + bih[h];
        float xz = g_gx[(size_t)(1024+h)*32+b]   + bih[1024+h];
        float xn = g_gx[(size_t)(2048+h)*32+b]   + bih[2048+h];
        float hr = g_gh[(size_t)h*32+b]          + bhh[h];
        float hz = g_gh[(size_t)(1024+h)*32+b]   + bhh[1024+h];
        float hn = g_gh[(size_t)(2048+h)*32+b]   + bhh[2048+h];
        float rr = 1.0f/(1.0f+expf(-(xr+hr)));
        float zz = 1.0f/(1.0f+expf(-(xz+hz)));
        float nn = tanhf(xn + rr*hn);
        g_decT[h*32+b] = (1.0f-zz)*nn + zz*hid[b*1024+h];
    }
    gsync();

    // ---- S2: v gemm -> RED into g_v[b][e] ----
    if (bid < 128){
        int kc = bid >> 2, e0 = (bid & 3) * 256;
        int k0 = kc * 32;
        for (int idx = tid; idx < 1024; idx += NT){
            int k = idx >> 5, b = idx & 31;
            smU[k*USTRIDE + b] = g_decT[(k0+k)*32 + b];
        }
        __syncthreads();
        if (tid < 256){
            int e = e0 + tid;
            const float* wp = Wattn + (size_t)k0*2048 + 1024 + e;
            u64 acc[16];
            #pragma unroll
            for (int p = 0; p < 16; p++) acc[p] = 0;
            #pragma unroll 8
            for (int k = 0; k < 32; k++){
                u64 wd = dup2(wp[(size_t)k*2048]);
                #pragma unroll
                for (int p = 0; p < 16; p += 2){
                    double2 u2 = *(const double2*)(smU + k*USTRIDE + 2*p);
                    FMA2(acc[p],   wd, d2u(u2.x));
                    FMA2(acc[p+1], wd, d2u(u2.y));
                }
            }
            #pragma unroll
            for (int p = 0; p < 16; p++){
                float lo, hi; unpk(acc[p], lo, hi);
                atomicAdd(&g_v[(size_t)(2*p  )*1024 + e], lo);
                atomicAdd(&g_v[(size_t)(2*p+1)*1024 + e], hi);
            }
        }
    }
    gsync();

    // ---- S4: scores (block-balanced warp units) ----
    for (int u = gws; u < 4096; u += NB*16){
        int b = u & 31, s = u >> 5;
        const float4* ep = (const float4*)(enc + (size_t)(s*32+b)*1024);
        const float4* vp = (const float4*)(g_v + b*1024);
        float a = 0.0f;
        #pragma unroll
        for (int i = 0; i < 8; i++){
            float4 e4 = ep[i*32 + lane];
            float4 v4 = vp[i*32 + lane];
            a += e4.x*v4.x + e4.y*v4.y + e4.z*v4.z + e4.w*v4.w;
        }
        #pragma unroll
        for (int o = 16; o; o >>= 1) a += __shfl_xor_sync(0xFFFFFFFFu, a, o);
        if (lane == 0) g_scores[b*128 + s] = a;
    }
    gsync();

    // ---- S5: softmax + attn weights out ----
    if (gws < 32){
        int b = gws;
        float v0 = g_scores[b*128 + lane];
        float v1 = g_scores[b*128 + 32 + lane];
        float v2 = g_scores[b*128 + 64 + lane];
        float v3 = g_scores[b*128 + 96 + lane];
        float m = fmaxf(fmaxf(v0,v1), fmaxf(v2,v3));
        #pragma unroll
        for (int o = 16; o; o >>= 1) m = fmaxf(m, __shfl_xor_sync(0xFFFFFFFFu, m, o));
        float e0 = expf(v0-m), e1 = expf(v1-m), e2 = expf(v2-m), e3 = expf(v3-m);
        float s = e0+e1+e2+e3;
        #pragma unroll
        for (int o = 16; o; o >>= 1) s += __shfl_xor_sync(0xFFFFFFFFu, s, o);
        float inv = 1.0f / s;
        float w0 = e0*inv, w1 = e1*inv, w2 = e2*inv, w3 = e3*inv;
        g_attw[b*128 + lane]      = w0;  out[(size_t)B_*V_ + b*128 + lane]      = w0;
        g_attw[b*128 + 32 + lane] = w1;  out[(size_t)B_*V_ + b*128 + 32 + lane] = w1;
        g_attw[b*128 + 64 + lane] = w2;  out[(size_t)B_*V_ + b*128 + 64 + lane] = w2;
        g_attw[b*128 + 96 + lane] = w3;  out[(size_t)B_*V_ + b*128 + 96 + lane] = w3;
    }
    gsync();

    // ---- S6: context ----
    if (gtid < 32768){
        int b = gtid >> 10, e = gtid & 1023;
        const float* ep = enc + (size_t)b*1024 + e;
        const float* wsp = g_attw + b*128;
        float a = 0.0f;
        #pragma unroll 16
        for (int s = 0; s < 128; s++) a += wsp[s] * ep[(size_t)s*32768];
        g_ctx[e*32 + b] = a;
    }
    gsync();

    // ---- S7: comb gemm -> RED into g_outU (pre-initialized with bcomb) ----
    if (bid < 128){
        int kc = bid >> 3, rc = bid & 7;
        int k0 = kc * 128;
        if (kc < 8){
            for (int idx = tid; idx < 128*32; idx += NT){
                int b = idx >> 7, kk = idx & 127;
                smU[kk*USTRIDE + b] = x[b*1024 + k0 + kk];
            }
        } else {
            for (int idx = tid; idx < 128*32; idx += NT){
                int kk = idx >> 5, b = idx & 31;
                smU[kk*USTRIDE + b] = g_ctx[(k0 - 1024 + kk)*32 + b];
            }
        }
        __syncthreads();
        if (wid < 8){
            int urow0 = rc*128 + wid*16;
            int row0 = urow0 + rg*4;
            const float4* w0 = (const float4*)(Wcomb + (size_t)(row0+0)*2048 + k0) + par;
            const float4* w1 = (const float4*)(Wcomb + (size_t)(row0+1)*2048 + k0) + par;
            const float4* w2 = (const float4*)(Wcomb + (size_t)(row0+2)*2048 + k0) + par;
            const float4* w3 = (const float4*)(Wcomb + (size_t)(row0+3)*2048 + k0) + par;
            u64 acc[16];
            #pragma unroll
            for (int p = 0; p < 16; p++) acc[p] = 0;
            float4 a0 = w0[0], a1 = w1[0], a2 = w2[0], a3 = w3[0];
            #pragma unroll
            for (int j = 0; j < 16; j++){
                float4 c0 = a0, c1 = a1, c2 = a2, c3 = a3;
                if (j + 1 < 16){
                    a0 = w0[2*(j+1)]; a1 = w1[2*(j+1)];
                    a2 = w2[2*(j+1)]; a3 = w3[2*(j+1)];
                }
                rb_j(c0, c1, c2, c3, smU + ((2*j+par)*4)*USTRIDE + bq*8, acc);
            }
            rb_stage(stW, acc, rg, bq, par);
            #pragma unroll
            for (int r2 = 0; r2 < 16; r2++){
                float v = stW[r2*34 + lane] + stW[16*34 + r2*34 + lane];
                atomicAdd(&g_outU[(size_t)(urow0 + r2)*32 + lane], v);
            }
            __syncwarp();
        }
    }
    gsync();

    // ---- S9: W_out gemm via mma.sync m16n8k16 bf16 (hi/lo split, 3 MMAs) ----
    {
        uint4* Bs = (uint4*)smU;   // [ks*4 + g][lane], g: 0=b0hi 1=b1hi 2=b0lo 3=b1lo (128KB)
        for (int idx = tid; idx < 4096; idx += NT){
            int l = idx & 31, rest = idx >> 5;
            int ks = rest >> 1, reg = rest & 1;
            int kb = ks*16 + (l&3)*2 + reg*8;
            int nb = l >> 2;
            uint4 hv, lv; unsigned h, lo;
            split2(g_outU[kb*32 + nb],      g_outU[(kb+1)*32 + nb],      h, lo); hv.x = h; lv.x = lo;
            split2(g_outU[kb*32 + nb + 8],  g_outU[(kb+1)*32 + nb + 8],  h, lo); hv.y = h; lv.y = lo;
            split2(g_outU[kb*32 + nb + 16], g_outU[(kb+1)*32 + nb + 16], h, lo); hv.z = h; lv.z = lo;
            split2(g_outU[kb*32 + nb + 24], g_outU[(kb+1)*32 + nb + 24], h, lo); hv.w = h; lv.w = lo;
            Bs[(ks*4 + reg)*32 + l]     = hv;
            Bs[(ks*4 + 2 + reg)*32 + l] = lv;
        }
        __syncthreads();

        for (int wu = gws; wu < 2000; wu += NB*16){
            int v0 = wu * 16;
            int r = lane >> 2, c = (lane & 3) * 2;
            const float* p0 = Wout + (size_t)(v0 + r)*1024 + c;
            const float* p1 = Wout + (size_t)(v0 + r + 8)*1024 + c;
            float acc[4][4];
            #pragma unroll
            for (int nt = 0; nt < 4; nt++)
                #pragma unroll
                for (int i = 0; i < 4; i++) acc[nt][i] = 0.0f;

            float2 fA[4][4];                 // depth-4 prefetch ring
            #pragma unroll
            for (int s = 0; s < 4; s++){
                const float* q0 = p0 + s*16;
                const float* q1 = p1 + s*16;
                fA[s][0] = *(const float2*)(q0);
                fA[s][1] = *(const float2*)(q1);
                fA[s][2] = *(const float2*)(q0 + 8);
                fA[s][3] = *(const float2*)(q1 + 8);
            }

            #pragma unroll 4
            for (int ks = 0; ks < 64; ks++){
                int sl = ks & 3;
                float2 g0 = fA[sl][0], g1 = fA[sl][1], g2 = fA[sl][2], g3 = fA[sl][3];
                if (ks + 4 < 64){
                    const float* q0 = p0 + (ks+4)*16;
                    const float* q1 = p1 + (ks+4)*16;
                    fA[sl][0] = *(const float2*)(q0);
                    fA[sl][1] = *(const float2*)(q1);
                    fA[sl][2] = *(const float2*)(q0 + 8);
                    fA[sl][3] = *(const float2*)(q1 + 8);
                }
                unsigned ah[4], al[4];
                split2(g0.x, g0.y, ah[0], al[0]);
                split2(g1.x, g1.y, ah[1], al[1]);
                split2(g2.x, g2.y, ah[2], al[2]);
                split2(g3.x, g3.y, ah[3], al[3]);
                uint4* Bsl = (uint4*)smU;
                {
                    uint4 bh0 = Bsl[(ks*4+0)*32 + lane];
                    uint4 bh1 = Bsl[(ks*4+1)*32 + lane];
                    MMA16816(acc[0], ah, bh0.x, bh1.x);
                    MMA16816(acc[0], al, bh0.x, bh1.x);
                    MMA16816(acc[1], ah, bh0.y, bh1.y);
                    MMA16816(acc[1], al, bh0.y, bh1.y);
                    MMA16816(acc[2], ah, bh0.z, bh1.z);
                    MMA16816(acc[2], al, bh0.z, bh1.z);
                    MMA16816(acc[3], ah, bh0.w, bh1.w);
                    MMA16816(acc[3], al, bh0.w, bh1.w);
                }
                {
                    uint4 bl0 = Bsl[(ks*4+2)*32 + lane];
                    uint4 bl1 = Bsl[(ks*4+3)*32 + lane];
                    MMA16816(acc[0], ah, bl0.x, bl1.x);
                    MMA16816(acc[1], ah, bl0.y, bl1.y);
                    MMA16816(acc[2], ah, bl0.z, bl1.z);
                    MMA16816(acc[3], ah, bl0.w, bl1.w);
                }
            }

            float bb0 = bout[v0 + r], bb1 = bout[v0 + r + 8];
            #pragma unroll
            for (int nt = 0; nt < 4; nt++){
                int jg = nt*8 + c;
                g_logits[(size_t)jg*V_     + v0 + r]     = acc[nt][0] + bb0;
                g_logits[(size_t)(jg+1)*V_ + v0 + r]     = acc[nt][1] + bb0;
                g_logits[(size_t)jg*V_     + v0 + r + 8] = acc[nt][2] + bb1;
                g_logits[(size_t)(jg+1)*V_ + v0 + r + 8] = acc[nt][3] + bb1;
            }
        }
    }
    gsync();

    // ---- S10: log-softmax partial sums (logits bounded; no max pass) ----
    if (gws < 256){
        int b = gws >> 3, c = gws & 7;
        const float* p0 = g_logits + (size_t)b*V_ + c*4000;
        float s0 = 0.0f, s1 = 0.0f;
        #pragma unroll 4
        for (int j = 0; j < 62; j++){
            s0 += __expf(p0[j*32 + lane]);
            s1 += __expf(p0[(j+62)*32 + lane]);
        }
        s0 += __expf(p0[124*32 + lane]);
        float s = s0 + s1;
        #pragma unroll
        for (int o = 16; o; o >>= 1) s += __shfl_xor_sync(0xFFFFFFFFu, s, o);
        if (lane == 0) g_ps[gws] = s;
    }
    gsync();

    // ---- S11+S12: per-block combine (redundant) + final write ----
    if (tid < 32){
        float S = 0.0f;
        #pragma unroll
        for (int c = 0; c < 8; c++) S += g_ps[tid*8 + c];
        smU[tid] = logf(S);
    }
    __syncthreads();
    for (int u = gtid; u < 256000; u += NB*NT){
        int b = u / 8000, r = u - b*8000;
        float4 a = ((const float4*)(g_logits + (size_t)b*V_))[r];
        float off = smU[b];
        ((float4*)(out + (size_t)b*V_))[r] =
            make_float4(a.x-off, a.y-off, a.z-off, a.w-off);
    }
}

// ---------------- launch ----------------
extern "C" void kernel_launch(void* const* d_in, const int* in_sizes, int n_in,
                              void* d_out, int out_size)
{
    const float* x     = (const float*)d_in[0];
    const float* enc   = (const float*)d_in[1];
    const float* hid   = (const float*)d_in[2];
    const float* Wih   = (const float*)d_in[3];
    const float* Whh   = (const float*)d_in[4];
    const float* bih   = (const float*)d_in[5];
    const float* bhh   = (const float*)d_in[6];
    const float* Wattn = (const float*)d_in[7];
    // d_in[8] = b_attn: softmax-invariant, unused
    const float* Wcomb = (const float*)d_in[9];
    const float* bcomb = (const float*)d_in[10];
    const float* Wout  = (const float*)d_in[11];
    const float* bout  = (const float*)d_in[12];
    float* out = (float*)d_out;

    static bool once = false;
    if (!once){
        cudaFuncSetAttribute(k_fused, cudaFuncAttributeMaxDynamicSharedMemorySize, SMEM_BYTES);
        once = true;
    }
    k_fused<<<NB, NT, SMEM_BYTES>>>(x, enc, hid, Wih, Whh, bih, bhh,
                                    Wattn, Wcomb, bcomb, Wout, bout, out);
}

// round 13
// speedup vs baseline: 1.1198x; 1.0045x over previous
#include <cuda_runtime.h>
#include <math.h>

#define B_ 32
#define S_ 128
#define V_ 32000
#define NB 148
#define NT 512
#define USTRIDE 36
#define SMU_FLOATS (1024*USTRIDE)
#define SMT_WARP   (2*16*34)
#define SMEM_BYTES ((SMU_FLOATS + 16*SMT_WARP)*4)   // 217088

typedef unsigned long long u64;

// ---------------- scratch ----------------
__device__ __align__(16) float g_gx[3072*32];         // x-gate accumulator [row][b]
__device__ __align__(16) float g_gh[3072*32];         // h-gate accumulator [row][b]
__device__ __align__(16) float g_decT[1024*32];       // [h][b]
__device__ __align__(16) float g_v[32*1024];          // [b][e] (atomic-accumulated)
__device__ __align__(16) float g_scores[32*128];
__device__ __align__(16) float g_attw[32*128];
__device__ __align__(16) float g_ctx[1024*32];        // [e][b]
__device__ __align__(16) float g_outU[1024*32];       // [k][b] (init=bcomb, atomic-accumulated)
__device__ __align__(16) float g_logits[32*32000];    // [b][v]
__device__ float g_psb[32];                           // per-b exp-sum (atomic)

// ---------------- grid barrier ----------------
__device__ unsigned g_bar_cnt;
__device__ volatile unsigned g_bar_gen;

__device__ __forceinline__ void gsync(){
    __syncthreads();
    if (threadIdx.x == 0){
        unsigned target = g_bar_gen + 1u;
        __threadfence();
        if (atomicAdd(&g_bar_cnt, 1u) == NB - 1u){
            g_bar_cnt = 0u;
            __threadfence();
            g_bar_gen = target;
        } else {
            while ((int)(g_bar_gen - target) < 0) __nanosleep(64);
            __threadfence();
        }
    }
    __syncthreads();
}

// ---------------- f32x2 helpers ----------------
#define FMA2(acc,a,b) asm("fma.rn.f32x2 %0, %1, %2, %0;" : "+l"(acc) : "l"(a), "l"(b))
__device__ __forceinline__ u64 dup2(float w){ u64 r; asm("mov.b64 %0, {%1, %1};" : "=l"(r) : "f"(w)); return r; }
__device__ __forceinline__ u64 d2u(double d){ return (u64)__double_as_longlong(d); }
__device__ __forceinline__ void unpk(u64 v, float& a, float& b){ asm("mov.b64 {%0,%1}, %2;" : "=f"(a), "=f"(b) : "l"(v)); }
#define PREF_L2(p) asm volatile("prefetch.global.L2 [%0];" :: "l"(p))

__device__ __forceinline__ void rb_k(float w0, float w1, float w2, float w3,
                                     const float* Ub, u64 acc[16]){
    double2 ua = *(const double2*)(Ub);
    double2 ub = *(const double2*)(Ub + 4);
    u64 u0 = d2u(ua.x), u1 = d2u(ua.y), u2 = d2u(ub.x), u3 = d2u(ub.y);
    u64 d0 = dup2(w0), d1 = dup2(w1), d2 = dup2(w2), d3 = dup2(w3);
    FMA2(acc[0],  d0, u0); FMA2(acc[1],  d0, u1); FMA2(acc[2],  d0, u2); FMA2(acc[3],  d0, u3);
    FMA2(acc[4],  d1, u0); FMA2(acc[5],  d1, u1); FMA2(acc[6],  d1, u2); FMA2(acc[7],  d1, u3);
    FMA2(acc[8],  d2, u0); FMA2(acc[9],  d2, u1); FMA2(acc[10], d2, u2); FMA2(acc[11], d2, u3);
    FMA2(acc[12], d3, u0); FMA2(acc[13], d3, u1); FMA2(acc[14], d3, u2); FMA2(acc[15], d3, u3);
}

__device__ __forceinline__ void rb_j(float4 c0, float4 c1, float4 c2, float4 c3,
                                     const float* Ub, u64 acc[16]){
    rb_k(c0.x, c1.x, c2.x, c3.x, Ub,             acc);
    rb_k(c0.y, c1.y, c2.y, c3.y, Ub + USTRIDE,   acc);
    rb_k(c0.z, c1.z, c2.z, c3.z, Ub + 2*USTRIDE, acc);
    rb_k(c0.w, c1.w, c2.w, c3.w, Ub + 3*USTRIDE, acc);
}

__device__ __forceinline__ void rb_stage(float* st, const u64 acc[16], int rg, int bq, int par){
    float* s = st + par*(16*34);
    #pragma unroll
    for (int i = 0; i < 4; i++){
        #pragma unroll
        for (int p = 0; p < 4; p++){
            float lo, hi; unpk(acc[i*4+p], lo, hi);
            *(float2*)(s + (rg*4+i)*34 + bq*8 + 2*p) = make_float2(lo, hi);
        }
    }
    __syncwarp();
}

// split fp32 -> bf16 hi (truncate) pair + bf16 lo (rounded residual) pair
__device__ __forceinline__ void split2(float w0, float w1, unsigned& h2, unsigned& l2){
    unsigned u0 = __float_as_uint(w0), u1 = __float_as_uint(w1);
    h2 = __byte_perm(u0, u1, 0x7632);
    float l0 = w0 - __uint_as_float(u0 & 0xFFFF0000u);
    float l1 = w1 - __uint_as_float(u1 & 0xFFFF0000u);
    asm("cvt.rn.bf16x2.f32 %0, %1, %2;" : "=r"(l2) : "f"(l1), "f"(l0));
}

// m16n8k16 bf16 mma, f32 accumulate (base-arch instruction, sm_80+)
#define MMA16816(c, a, b0r, b1r) \
    asm volatile("mma.sync.aligned.m16n8k16.row.col.f32.bf16.bf16.f32 " \
        "{%0,%1,%2,%3}, {%4,%5,%6,%7}, {%8,%9}, {%0,%1,%2,%3};" \
        : "+f"((c)[0]), "+f"((c)[1]), "+f"((c)[2]), "+f"((c)[3]) \
        : "r"((a)[0]), "r"((a)[1]), "r"((a)[2]), "r"((a)[3]), "r"(b0r), "r"(b1r))

// ================= fused kernel =================
__global__ void __launch_bounds__(NT, 1) k_fused(
    const float* __restrict__ x, const float* __restrict__ enc,
    const float* __restrict__ hid,
    const float* __restrict__ Wih, const float* __restrict__ Whh,
    const float* __restrict__ bih, const float* __restrict__ bhh,
    const float* __restrict__ Wattn,
    const float* __restrict__ Wcomb, const float* __restrict__ bcomb,
    const float* __restrict__ Wout, const float* __restrict__ bout,
    float* __restrict__ out)
{
    extern __shared__ float smU[];
    float* smT = smU + SMU_FLOATS;
    const int bid = blockIdx.x, tid = threadIdx.x;
    const int wid = tid >> 5, lane = tid & 31;
    const int gtid = bid * NT + tid;
    const int gws = wid * NB + bid;     // block-balanced warp unit id
    const int rg  = lane >> 3;
    const int bq  = (lane >> 1) & 3;
    const int par = lane & 1;
    float* stW = smT + wid * SMT_WARP;

    // ---- Sinit: zero accumulators; init g_outU = bcomb ----
    for (int u = gtid; u < 3072*32; u += NB*NT){ g_gx[u] = 0.0f; g_gh[u] = 0.0f; }
    for (int u = gtid; u < 32768; u += NB*NT){
        g_v[u] = 0.0f;
        g_outU[u] = bcomb[u >> 5];
    }
    if (gtid < 32) g_psb[gtid] = 0.0f;
    gsync();

    // ---- S0: GRU gemm partials -> RED into g_gx / g_gh ----
    if (bid < 128){
        int mat = bid >> 6, r = bid & 63;
        int kc = r >> 4, vb = r & 15;
        const float* W   = mat ? Whh : Wih;
        const float* src = mat ? hid : x;
        int k0 = kc * 256;
        for (int idx = tid; idx < 256*32; idx += NT){
            int b = idx >> 8, kk = idx & 255;
            smU[kk*USTRIDE + b] = src[b*1024 + k0 + kk];
        }
        __syncthreads();
        if (wid < 12){
            int urow0 = vb*192 + wid*16;
            int row0 = urow0 + rg*4;
            const float4* w0 = (const float4*)(W + (size_t)(row0+0)*1024 + k0) + par;
            const float4* w1 = (const float4*)(W + (size_t)(row0+1)*1024 + k0) + par;
            const float4* w2 = (const float4*)(W + (size_t)(row0+2)*1024 + k0) + par;
            const float4* w3 = (const float4*)(W + (size_t)(row0+3)*1024 + k0) + par;
            u64 acc[16];
            #pragma unroll
            for (int p = 0; p < 16; p++) acc[p] = 0;
            float4 a0 = w0[0], a1 = w1[0], a2 = w2[0], a3 = w3[0];
            for (int j = 0; j < 32; j++){
                float4 c0 = a0, c1 = a1, c2 = a2, c3 = a3;
                if (j + 1 < 32){
                    a0 = w0[2*(j+1)]; a1 = w1[2*(j+1)];
                    a2 = w2[2*(j+1)]; a3 = w3[2*(j+1)];
                }
                rb_j(c0, c1, c2, c3, smU + ((2*j+par)*4)*USTRIDE + bq*8, acc);
            }
            rb_stage(stW, acc, rg, bq, par);
            float* P = mat ? g_gh : g_gx;
            #pragma unroll
            for (int r2 = 0; r2 < 16; r2++){
                float v = stW[r2*34 + lane] + stW[16*34 + r2*34 + lane];
                atomicAdd(&P[(size_t)(urow0 + r2)*32 + lane], v);
            }
            __syncwarp();
        }
    }
    gsync();

    // ---- S1: GRU activation -> decT[h][b] ----
    if (gtid < 32768){
        int h = gtid >> 5, b = gtid & 31;
        float xr = g_gx[(size_t)h*32+b]          + bih[h];
        float xz = g_gx[(size_t)(1024+h)*32+b]   + bih[1024+h];
        float xn = g_gx[(size_t)(2048+h)*32+b]   + bih[2048+h];
        float hr = g_gh[(size_t)h*32+b]          + bhh[h];
        float hz = g_gh[(size_t)(1024+h)*32+b]   + bhh[1024+h];
        float hn = g_gh[(size_t)(2048+h)*32+b]   + bhh[2048+h];
        float rr = 1.0f/(1.0f+expf(-(xr+hr)));
        float zz = 1.0f/(1.0f+expf(-(xz+hz)));
        float nn = tanhf(xn + rr*hn);
        g_decT[h*32+b] = (1.0f-zz)*nn + zz*hid[b*1024+h];
    }
    gsync();

    // ---- S2: v gemm -> RED into g_v[b][e]; idle blocks prefetch enc to L2 ----
    if (bid < 128){
        int kc = bid >> 2, e0 = (bid & 3) * 256;
        int k0 = kc * 32;
        for (int idx = tid; idx < 1024; idx += NT){
            int k = idx >> 5, b = idx & 31;
            smU[k*USTRIDE + b] = g_decT[(k0+k)*32 + b];
        }
        __syncthreads();
        if (tid < 256){
            int e = e0 + tid;
            const float* wp = Wattn + (size_t)k0*2048 + 1024 + e;
            u64 acc[16];
            #pragma unroll
            for (int p = 0; p < 16; p++) acc[p] = 0;
            #pragma unroll 8
            for (int k = 0; k < 32; k++){
                u64 wd = dup2(wp[(size_t)k*2048]);
                #pragma unroll
                for (int p = 0; p < 16; p += 2){
                    double2 u2 = *(const double2*)(smU + k*USTRIDE + 2*p);
                    FMA2(acc[p],   wd, d2u(u2.x));
                    FMA2(acc[p+1], wd, d2u(u2.y));
                }
            }
            #pragma unroll
            for (int p = 0; p < 16; p++){
                float lo, hi; unpk(acc[p], lo, hi);
                atomicAdd(&g_v[(size_t)(2*p  )*1024 + e], lo);
                atomicAdd(&g_v[(size_t)(2*p+1)*1024 + e], hi);
            }
        }
    } else {
        // blocks 128-147: prefetch enc (16MB = 131072 lines of 128B)
        for (int L = (bid - 128)*NT + tid; L < 131072; L += 20*NT)
            PREF_L2(enc + (size_t)L*32);
    }
    gsync();

    // ---- S4: scores ----
    for (int u = gws; u < 4096; u += NB*16){
        int b = u & 31, s = u >> 5;
        const float4* ep = (const float4*)(enc + (size_t)(s*32+b)*1024);
        const float4* vp = (const float4*)(g_v + b*1024);
        float a = 0.0f;
        #pragma unroll
        for (int i = 0; i < 8; i++){
            float4 e4 = ep[i*32 + lane];
            float4 v4 = vp[i*32 + lane];
            a += e4.x*v4.x + e4.y*v4.y + e4.z*v4.z + e4.w*v4.w;
        }
        #pragma unroll
        for (int o = 16; o; o >>= 1) a += __shfl_xor_sync(0xFFFFFFFFu, a, o);
        if (lane == 0) g_scores[b*128 + s] = a;
    }
    gsync();

    // ---- S5: softmax + attn weights out ----
    if (gws < 32){
        int b = gws;
        float v0 = g_scores[b*128 + lane];
        float v1 = g_scores[b*128 + 32 + lane];
        float v2 = g_scores[b*128 + 64 + lane];
        float v3 = g_scores[b*128 + 96 + lane];
        float m = fmaxf(fmaxf(v0,v1), fmaxf(v2,v3));
        #pragma unroll
        for (int o = 16; o; o >>= 1) m = fmaxf(m, __shfl_xor_sync(0xFFFFFFFFu, m, o));
        float e0 = expf(v0-m), e1 = expf(v1-m), e2 = expf(v2-m), e3 = expf(v3-m);
        float s = e0+e1+e2+e3;
        #pragma unroll
        for (int o = 16; o; o >>= 1) s += __shfl_xor_sync(0xFFFFFFFFu, s, o);
        float inv = 1.0f / s;
        float w0 = e0*inv, w1 = e1*inv, w2 = e2*inv, w3 = e3*inv;
        g_attw[b*128 + lane]      = w0;  out[(size_t)B_*V_ + b*128 + lane]      = w0;
        g_attw[b*128 + 32 + lane] = w1;  out[(size_t)B_*V_ + b*128 + 32 + lane] = w1;
        g_attw[b*128 + 64 + lane] = w2;  out[(size_t)B_*V_ + b*128 + 64 + lane] = w2;
        g_attw[b*128 + 96 + lane] = w3;  out[(size_t)B_*V_ + b*128 + 96 + lane] = w3;
    }
    gsync();

    // ---- S6: context; idle blocks (64-147) prefetch Wout to L2 ----
    if (gtid < 32768){
        int b = gtid >> 10, e = gtid & 1023;
        const float* ep = enc + (size_t)b*1024 + e;
        const float* wsp = g_attw + b*128;
        float a = 0.0f;
        #pragma unroll 16
        for (int s = 0; s < 128; s++) a += wsp[s] * ep[(size_t)s*32768];
        g_ctx[e*32 + b] = a;
    } else {
        // Wout = 131072KB = 1024000 lines of 128B; 1344 prefetch warps
        int q = (bid - 64)*16 + wid;           // 0..1343
        int start = q * 762;
        int end = start + 762; if (end > 1024000) end = 1024000;
        for (int L = start + lane; L < end; L += 32)
            PREF_L2(Wout + (size_t)L*32);
    }
    gsync();

    // ---- S7: comb gemm -> RED into g_outU (pre-initialized with bcomb) ----
    if (bid < 128){
        int kc = bid >> 3, rc = bid & 7;
        int k0 = kc * 128;
        if (kc < 8){
            for (int idx = tid; idx < 128*32; idx += NT){
                int b = idx >> 7, kk = idx & 127;
                smU[kk*USTRIDE + b] = x[b*1024 + k0 + kk];
            }
        } else {
            for (int idx = tid; idx < 128*32; idx += NT){
                int kk = idx >> 5, b = idx & 31;
                smU[kk*USTRIDE + b] = g_ctx[(k0 - 1024 + kk)*32 + b];
            }
        }
        __syncthreads();
        if (wid < 8){
            int urow0 = rc*128 + wid*16;
            int row0 = urow0 + rg*4;
            const float4* w0 = (const float4*)(Wcomb + (size_t)(row0+0)*2048 + k0) + par;
            const float4* w1 = (const float4*)(Wcomb + (size_t)(row0+1)*2048 + k0) + par;
            const float4* w2 = (const float4*)(Wcomb + (size_t)(row0+2)*2048 + k0) + par;
            const float4* w3 = (const float4*)(Wcomb + (size_t)(row0+3)*2048 + k0) + par;
            u64 acc[16];
            #pragma unroll
            for (int p = 0; p < 16; p++) acc[p] = 0;
            float4 a0 = w0[0], a1 = w1[0], a2 = w2[0], a3 = w3[0];
            #pragma unroll
            for (int j = 0; j < 16; j++){
                float4 c0 = a0, c1 = a1, c2 = a2, c3 = a3;
                if (j + 1 < 16){
                    a0 = w0[2*(j+1)]; a1 = w1[2*(j+1)];
                    a2 = w2[2*(j+1)]; a3 = w3[2*(j+1)];
                }
                rb_j(c0, c1, c2, c3, smU + ((2*j+par)*4)*USTRIDE + bq*8, acc);
            }
            rb_stage(stW, acc, rg, bq, par);
            #pragma unroll
            for (int r2 = 0; r2 < 16; r2++){
                float v = stW[r2*34 + lane] + stW[16*34 + r2*34 + lane];
                atomicAdd(&g_outU[(size_t)(urow0 + r2)*32 + lane], v);
            }
            __syncwarp();
        }
    }
    gsync();

    // ---- S9: W_out gemm via mma.sync + fused exp-sum epilogue ----
    {
        uint4* Bs = (uint4*)smU;   // [ks*4 + g][lane] (128KB)
        for (int idx = tid; idx < 4096; idx += NT){
            int l = idx & 31, rest = idx >> 5;
            int ks = rest >> 1, reg = rest & 1;
            int kb = ks*16 + (l&3)*2 + reg*8;
            int nb = l >> 2;
            uint4 hv, lv; unsigned h, lo;
            split2(g_outU[kb*32 + nb],      g_outU[(kb+1)*32 + nb],      h, lo); hv.x = h; lv.x = lo;
            split2(g_outU[kb*32 + nb + 8],  g_outU[(kb+1)*32 + nb + 8],  h, lo); hv.y = h; lv.y = lo;
            split2(g_outU[kb*32 + nb + 16], g_outU[(kb+1)*32 + nb + 16], h, lo); hv.z = h; lv.z = lo;
            split2(g_outU[kb*32 + nb + 24], g_outU[(kb+1)*32 + nb + 24], h, lo); hv.w = h; lv.w = lo;
            Bs[(ks*4 + reg)*32 + l]     = hv;
            Bs[(ks*4 + 2 + reg)*32 + l] = lv;
        }
        if (tid < 32) smT[tid] = 0.0f;     // per-block exp-sum accumulator
        __syncthreads();

        for (int wu = gws; wu < 2000; wu += NB*16){
            int v0 = wu * 16;
            int r = lane >> 2, c = (lane & 3) * 2;
            const float* p0 = Wout + (size_t)(v0 + r)*1024 + c;
            const float* p1 = Wout + (size_t)(v0 + r + 8)*1024 + c;
            float acc[4][4];
            #pragma unroll
            for (int nt = 0; nt < 4; nt++)
                #pragma unroll
                for (int i = 0; i < 4; i++) acc[nt][i] = 0.0f;

            float2 fA[4][4];                 // depth-4 prefetch ring
            #pragma unroll
            for (int s = 0; s < 4; s++){
                const float* q0 = p0 + s*16;
                const float* q1 = p1 + s*16;
                fA[s][0] = *(const float2*)(q0);
                fA[s][1] = *(const float2*)(q1);
                fA[s][2] = *(const float2*)(q0 + 8);
                fA[s][3] = *(const float2*)(q1 + 8);
            }

            #pragma unroll 4
            for (int ks = 0; ks < 64; ks++){
                int sl = ks & 3;
                float2 g0 = fA[sl][0], g1 = fA[sl][1], g2 = fA[sl][2], g3 = fA[sl][3];
                if (ks + 4 < 64){
                    const float* q0 = p0 + (ks+4)*16;
                    const float* q1 = p1 + (ks+4)*16;
                    fA[sl][0] = *(const float2*)(q0);
                    fA[sl][1] = *(const float2*)(q1);
                    fA[sl][2] = *(const float2*)(q0 + 8);
                    fA[sl][3] = *(const float2*)(q1 + 8);
                }
                unsigned ah[4], al[4];
                split2(g0.x, g0.y, ah[0], al[0]);
                split2(g1.x, g1.y, ah[1], al[1]);
                split2(g2.x, g2.y, ah[2], al[2]);
                split2(g3.x, g3.y, ah[3], al[3]);
                uint4* Bsl = (uint4*)smU;
                {
                    uint4 bh0 = Bsl[(ks*4+0)*32 + lane];
                    uint4 bh1 = Bsl[(ks*4+1)*32 + lane];
                    MMA16816(acc[0], ah, bh0.x, bh1.x);
                    MMA16816(acc[0], al, bh0.x, bh1.x);
                    MMA16816(acc[1], ah, bh0.y, bh1.y);
                    MMA16816(acc[1], al, bh0.y, bh1.y);
                    MMA16816(acc[2], ah, bh0.z, bh1.z);
                    MMA16816(acc[2], al, bh0.z, bh1.z);
                    MMA16816(acc[3], ah, bh0.w, bh1.w);
                    MMA16816(acc[3], al, bh0.w, bh1.w);
                }
                {
                    uint4 bl0 = Bsl[(ks*4+2)*32 + lane];
                    uint4 bl1 = Bsl[(ks*4+3)*32 + lane];
                    MMA16816(acc[0], ah, bl0.x, bl1.x);
                    MMA16816(acc[1], ah, bl0.y, bl1.y);
                    MMA16816(acc[2], ah, bl0.z, bl1.z);
                    MMA16816(acc[3], ah, bl0.w, bl1.w);
                }
            }

            float bb0 = bout[v0 + r], bb1 = bout[v0 + r + 8];
            float pb0[4], pb1[4];
            #pragma unroll
            for (int nt = 0; nt < 4; nt++){
                int jg = nt*8 + c;
                float x0 = acc[nt][0] + bb0;
                float x1 = acc[nt][1] + bb0;
                float x2 = acc[nt][2] + bb1;
                float x3 = acc[nt][3] + bb1;
                g_logits[(size_t)jg*V_     + v0 + r]     = x0;
                g_logits[(size_t)(jg+1)*V_ + v0 + r]     = x1;
                g_logits[(size_t)jg*V_     + v0 + r + 8] = x2;
                g_logits[(size_t)(jg+1)*V_ + v0 + r + 8] = x3;
                pb0[nt] = __expf(x0) + __expf(x2);   // b = jg
                pb1[nt] = __expf(x1) + __expf(x3);   // b = jg+1
            }
            // reduce over r (lane bits 2..4), then lanes<4 accumulate to smem
            #pragma unroll
            for (int o = 4; o <= 16; o <<= 1){
                #pragma unroll
                for (int nt = 0; nt < 4; nt++){
                    pb0[nt] += __shfl_xor_sync(0xFFFFFFFFu, pb0[nt], o);
                    pb1[nt] += __shfl_xor_sync(0xFFFFFFFFu, pb1[nt], o);
                }
            }
            if (lane < 4){
                #pragma unroll
                for (int nt = 0; nt < 4; nt++){
                    atomicAdd(&smT[nt*8 + c],     pb0[nt]);
                    atomicAdd(&smT[nt*8 + c + 1], pb1[nt]);
                }
            }
        }
        __syncthreads();
        if (tid < 32) atomicAdd(&g_psb[tid], smT[tid]);
    }
    gsync();

    // ---- S11+S12: off = log(sum) + final write ----
    if (tid < 32) smU[tid] = logf(g_psb[tid]);
    __syncthreads();
    for (int u = gtid; u < 256000; u += NB*NT){
        int b = u / 8000, r = u - b*8000;
        float4 a = ((const float4*)(g_logits + (size_t)b*V_))[r];
        float off = smU[b];
        ((float4*)(out + (size_t)b*V_))[r] =
            make_float4(a.x-off, a.y-off, a.z-off, a.w-off);
    }
}

// ---------------- launch ----------------
extern "C" void kernel_launch(void* const* d_in, const int* in_sizes, int n_in,
                              void* d_out, int out_size)
{
    const float* x     = (const float*)d_in[0];
    const float* enc   = (const float*)d_in[1];
    const float* hid   = (const float*)d_in[2];
    const float* Wih   = (const float*)d_in[3];
    const float* Whh   = (const float*)d_in[4];
    const float* bih   = (const float*)d_in[5];
    const float* bhh   = (const float*)d_in[6];
    const float* Wattn = (const float*)d_in[7];
    // d_in[8] = b_attn: softmax-invariant, unused
    const float* Wcomb = (const float*)d_in[9];
    const float* bcomb = (const float*)d_in[10];
    const float* Wout  = (const float*)d_in[11];
    const float* bout  = (const float*)d_in[12];
    float* out = (float*)d_out;

    static bool once = false;
    if (!once){
        cudaFuncSetAttribute(k_fused, cudaFuncAttributeMaxDynamicSharedMemorySize, SMEM_BYTES);
        once = true;
    }
    k_fused<<<NB, NT, SMEM_BYTES>>>(x, enc, hid, Wih, Whh, bih, bhh,
                                    Wattn, Wcomb, bcomb, Wout, bout, out);
}

// round 14
// speedup vs baseline: 1.1955x; 1.0676x over previous
#include <cuda_runtime.h>
#include <math.h>

#define B_ 32
#define S_ 128
#define V_ 32000
#define NB 148
#define NT 512
#define USTRIDE 36
#define SMU_FLOATS (1024*USTRIDE)
#define SMT_WARP   (2*16*34)
#define SMEM_BYTES ((SMU_FLOATS + 16*SMT_WARP)*4)   // 217088

typedef unsigned long long u64;

// ---------------- scratch ----------------
__device__ __align__(16) float g_gx[3072*32];         // x-gate accumulator [row][b]
__device__ __align__(16) float g_gh[3072*32];         // h-gate accumulator [row][b]
__device__ __align__(16) float g_decT[1024*32];       // [h][b]
__device__ __align__(16) float g_v[32*1024];          // [b][e] (atomic-accumulated)
__device__ __align__(16) float g_scores[32*128];
__device__ __align__(16) float g_attw[32*128];
__device__ __align__(16) float g_ctx[1024*32];        // [e][b]
__device__ __align__(16) float g_outU[1024*32];       // [k][b] (init=bcomb, atomic-accumulated)
__device__ __align__(16) float g_logits[32*32000];    // [b][v]
__device__ float g_psb[32];                           // per-b exp-sum (atomic)

// ---------------- grid barrier ----------------
__device__ unsigned g_bar_cnt;
__device__ volatile unsigned g_bar_gen;

__device__ __forceinline__ void gsync(){
    __syncthreads();
    if (threadIdx.x == 0){
        unsigned target = g_bar_gen + 1u;
        __threadfence();
        if (atomicAdd(&g_bar_cnt, 1u) == NB - 1u){
            g_bar_cnt = 0u;
            __threadfence();
            g_bar_gen = target;
        } else {
            while ((int)(g_bar_gen - target) < 0) __nanosleep(64);
            __threadfence();
        }
    }
    __syncthreads();
}

// ---------------- f32x2 helpers ----------------
#define FMA2(acc,a,b) asm("fma.rn.f32x2 %0, %1, %2, %0;" : "+l"(acc) : "l"(a), "l"(b))
__device__ __forceinline__ u64 dup2(float w){ u64 r; asm("mov.b64 %0, {%1, %1};" : "=l"(r) : "f"(w)); return r; }
__device__ __forceinline__ u64 d2u(double d){ return (u64)__double_as_longlong(d); }
__device__ __forceinline__ void unpk(u64 v, float& a, float& b){ asm("mov.b64 {%0,%1}, %2;" : "=f"(a), "=f"(b) : "l"(v)); }
#define PREF_L2(p) asm volatile("prefetch.global.L2 [%0];" :: "l"(p))

__device__ __forceinline__ void rb_k(float w0, float w1, float w2, float w3,
                                     const float* Ub, u64 acc[16]){
    double2 ua = *(const double2*)(Ub);
    double2 ub = *(const double2*)(Ub + 4);
    u64 u0 = d2u(ua.x), u1 = d2u(ua.y), u2 = d2u(ub.x), u3 = d2u(ub.y);
    u64 d0 = dup2(w0), d1 = dup2(w1), d2 = dup2(w2), d3 = dup2(w3);
    FMA2(acc[0],  d0, u0); FMA2(acc[1],  d0, u1); FMA2(acc[2],  d0, u2); FMA2(acc[3],  d0, u3);
    FMA2(acc[4],  d1, u0); FMA2(acc[5],  d1, u1); FMA2(acc[6],  d1, u2); FMA2(acc[7],  d1, u3);
    FMA2(acc[8],  d2, u0); FMA2(acc[9],  d2, u1); FMA2(acc[10], d2, u2); FMA2(acc[11], d2, u3);
    FMA2(acc[12], d3, u0); FMA2(acc[13], d3, u1); FMA2(acc[14], d3, u2); FMA2(acc[15], d3, u3);
}

__device__ __forceinline__ void rb_j(float4 c0, float4 c1, float4 c2, float4 c3,
                                     const float* Ub, u64 acc[16]){
    rb_k(c0.x, c1.x, c2.x, c3.x, Ub,             acc);
    rb_k(c0.y, c1.y, c2.y, c3.y, Ub + USTRIDE,   acc);
    rb_k(c0.z, c1.z, c2.z, c3.z, Ub + 2*USTRIDE, acc);
    rb_k(c0.w, c1.w, c2.w, c3.w, Ub + 3*USTRIDE, acc);
}

__device__ __forceinline__ void rb_stage(float* st, const u64 acc[16], int rg, int bq, int par){
    float* s = st + par*(16*34);
    #pragma unroll
    for (int i = 0; i < 4; i++){
        #pragma unroll
        for (int p = 0; p < 4; p++){
            float lo, hi; unpk(acc[i*4+p], lo, hi);
            *(float2*)(s + (rg*4+i)*34 + bq*8 + 2*p) = make_float2(lo, hi);
        }
    }
    __syncwarp();
}

// split fp32 -> bf16 hi (truncate) pair + bf16 lo (rounded residual) pair
__device__ __forceinline__ void split2(float w0, float w1, unsigned& h2, unsigned& l2){
    unsigned u0 = __float_as_uint(w0), u1 = __float_as_uint(w1);
    h2 = __byte_perm(u0, u1, 0x7632);
    float l0 = w0 - __uint_as_float(u0 & 0xFFFF0000u);
    float l1 = w1 - __uint_as_float(u1 & 0xFFFF0000u);
    asm("cvt.rn.bf16x2.f32 %0, %1, %2;" : "=r"(l2) : "f"(l1), "f"(l0));
}

// m16n8k16 bf16 mma, f32 accumulate (base-arch instruction, sm_80+)
#define MMA16816(c, a, b0r, b1r) \
    asm volatile("mma.sync.aligned.m16n8k16.row.col.f32.bf16.bf16.f32 " \
        "{%0,%1,%2,%3}, {%4,%5,%6,%7}, {%8,%9}, {%0,%1,%2,%3};" \
        : "+f"((c)[0]), "+f"((c)[1]), "+f"((c)[2]), "+f"((c)[3]) \
        : "r"((a)[0]), "r"((a)[1]), "r"((a)[2]), "r"((a)[3]), "r"(b0r), "r"(b1r))

// ================= fused kernel =================
__global__ void __launch_bounds__(NT, 1) k_fused(
    const float* __restrict__ x, const float* __restrict__ enc,
    const float* __restrict__ hid,
    const float* __restrict__ Wih, const float* __restrict__ Whh,
    const float* __restrict__ bih, const float* __restrict__ bhh,
    const float* __restrict__ Wattn,
    const float* __restrict__ Wcomb, const float* __restrict__ bcomb,
    const float* __restrict__ Wout, const float* __restrict__ bout,
    float* __restrict__ out)
{
    extern __shared__ float smU[];
    float* smT = smU + SMU_FLOATS;
    const int bid = blockIdx.x, tid = threadIdx.x;
    const int wid = tid >> 5, lane = tid & 31;
    const int gtid = bid * NT + tid;
    const int gws = wid * NB + bid;     // block-balanced warp unit id
    const int rg  = lane >> 3;
    const int bq  = (lane >> 1) & 3;
    const int par = lane & 1;
    float* stW = smT + wid * SMT_WARP;

    // ---- Sinit: zero accumulators; init g_outU = bcomb; prefetch GRU weights (24MB, fits L2) ----
    for (int u = gtid; u < 3072*32; u += NB*NT){ g_gx[u] = 0.0f; g_gh[u] = 0.0f; }
    for (int u = gtid; u < 32768; u += NB*NT){
        g_v[u] = 0.0f;
        g_outU[u] = bcomb[u >> 5];
    }
    if (gtid < 32) g_psb[gtid] = 0.0f;
    for (int L = gtid; L < 98304; L += NB*NT){   // 12MB each = 98304 lines of 128B
        PREF_L2(Wih + (size_t)L*32);
        PREF_L2(Whh + (size_t)L*32);
    }
    gsync();

    // ---- S0: GRU gemm partials -> RED into g_gx / g_gh ----
    if (bid < 128){
        int mat = bid >> 6, r = bid & 63;
        int kc = r >> 4, vb = r & 15;
        const float* W   = mat ? Whh : Wih;
        const float* src = mat ? hid : x;
        int k0 = kc * 256;
        for (int idx = tid; idx < 256*32; idx += NT){
            int b = idx >> 8, kk = idx & 255;
            smU[kk*USTRIDE + b] = src[b*1024 + k0 + kk];
        }
        __syncthreads();
        if (wid < 12){
            int urow0 = vb*192 + wid*16;
            int row0 = urow0 + rg*4;
            const float4* w0 = (const float4*)(W + (size_t)(row0+0)*1024 + k0) + par;
            const float4* w1 = (const float4*)(W + (size_t)(row0+1)*1024 + k0) + par;
            const float4* w2 = (const float4*)(W + (size_t)(row0+2)*1024 + k0) + par;
            const float4* w3 = (const float4*)(W + (size_t)(row0+3)*1024 + k0) + par;
            u64 acc[16];
            #pragma unroll
            for (int p = 0; p < 16; p++) acc[p] = 0;
            float4 a0 = w0[0], a1 = w1[0], a2 = w2[0], a3 = w3[0];
            for (int j = 0; j < 32; j++){
                float4 c0 = a0, c1 = a1, c2 = a2, c3 = a3;
                if (j + 1 < 32){
                    a0 = w0[2*(j+1)]; a1 = w1[2*(j+1)];
                    a2 = w2[2*(j+1)]; a3 = w3[2*(j+1)];
                }
                rb_j(c0, c1, c2, c3, smU + ((2*j+par)*4)*USTRIDE + bq*8, acc);
            }
            rb_stage(stW, acc, rg, bq, par);
            float* P = mat ? g_gh : g_gx;
            #pragma unroll
            for (int r2 = 0; r2 < 16; r2++){
                float v = stW[r2*34 + lane] + stW[16*34 + r2*34 + lane];
                atomicAdd(&P[(size_t)(urow0 + r2)*32 + lane], v);
            }
            __syncwarp();
        }
    }
    gsync();

    // ---- S1: GRU activation -> decT[h][b] ----
    if (gtid < 32768){
        int h = gtid >> 5, b = gtid & 31;
        float xr = g_gx[(size_t)h*32+b]          + bih[h];
        float xz = g_gx[(size_t)(1024+h)*32+b]   + bih[1024+h];
        float xn = g_gx[(size_t)(2048+h)*32+b]   + bih[2048+h];
        float hr = g_gh[(size_t)h*32+b]          + bhh[h];
        float hz = g_gh[(size_t)(1024+h)*32+b]   + bhh[1024+h];
        float hn = g_gh[(size_t)(2048+h)*32+b]   + bhh[2048+h];
        float rr = 1.0f/(1.0f+expf(-(xr+hr)));
        float zz = 1.0f/(1.0f+expf(-(xz+hz)));
        float nn = tanhf(xn + rr*hn);
        g_decT[h*32+b] = (1.0f-zz)*nn + zz*hid[b*1024+h];
    }
    gsync();

    // ---- S2: v gemm -> RED into g_v[b][e]; idle blocks prefetch enc + Wcomb ----
    if (bid < 128){
        int kc = bid >> 2, e0 = (bid & 3) * 256;
        int k0 = kc * 32;
        for (int idx = tid; idx < 1024; idx += NT){
            int k = idx >> 5, b = idx & 31;
            smU[k*USTRIDE + b] = g_decT[(k0+k)*32 + b];
        }
        __syncthreads();
        if (tid < 256){
            int e = e0 + tid;
            const float* wp = Wattn + (size_t)k0*2048 + 1024 + e;
            u64 acc[16];
            #pragma unroll
            for (int p = 0; p < 16; p++) acc[p] = 0;
            #pragma unroll 8
            for (int k = 0; k < 32; k++){
                u64 wd = dup2(wp[(size_t)k*2048]);
                #pragma unroll
                for (int p = 0; p < 16; p += 2){
                    double2 u2 = *(const double2*)(smU + k*USTRIDE + 2*p);
                    FMA2(acc[p],   wd, d2u(u2.x));
                    FMA2(acc[p+1], wd, d2u(u2.y));
                }
            }
            #pragma unroll
            for (int p = 0; p < 16; p++){
                float lo, hi; unpk(acc[p], lo, hi);
                atomicAdd(&g_v[(size_t)(2*p  )*1024 + e], lo);
                atomicAdd(&g_v[(size_t)(2*p+1)*1024 + e], hi);
            }
        }
    } else {
        // blocks 128-147 (10240 threads): prefetch enc (16MB) + Wcomb (8MB)
        int t0 = (bid - 128)*NT + tid;
        for (int L = t0; L < 131072; L += 20*NT)
            PREF_L2(enc + (size_t)L*32);
        for (int L = t0; L < 65536; L += 20*NT)
            PREF_L2(Wcomb + (size_t)L*32);
    }
    gsync();

    // ---- S4: scores ----
    for (int u = gws; u < 4096; u += NB*16){
        int b = u & 31, s = u >> 5;
        const float4* ep = (const float4*)(enc + (size_t)(s*32+b)*1024);
        const float4* vp = (const float4*)(g_v + b*1024);
        float a = 0.0f;
        #pragma unroll
        for (int i = 0; i < 8; i++){
            float4 e4 = ep[i*32 + lane];
            float4 v4 = vp[i*32 + lane];
            a += e4.x*v4.x + e4.y*v4.y + e4.z*v4.z + e4.w*v4.w;
        }
        #pragma unroll
        for (int o = 16; o; o >>= 1) a += __shfl_xor_sync(0xFFFFFFFFu, a, o);
        if (lane == 0) g_scores[b*128 + s] = a;
    }
    gsync();

    // ---- S5: softmax + attn weights out ----
    if (gws < 32){
        int b = gws;
        float v0 = g_scores[b*128 + lane];
        float v1 = g_scores[b*128 + 32 + lane];
        float v2 = g_scores[b*128 + 64 + lane];
        float v3 = g_scores[b*128 + 96 + lane];
        float m = fmaxf(fmaxf(v0,v1), fmaxf(v2,v3));
        #pragma unroll
        for (int o = 16; o; o >>= 1) m = fmaxf(m, __shfl_xor_sync(0xFFFFFFFFu, m, o));
        float e0 = expf(v0-m), e1 = expf(v1-m), e2 = expf(v2-m), e3 = expf(v3-m);
        float s = e0+e1+e2+e3;
        #pragma unroll
        for (int o = 16; o; o >>= 1) s += __shfl_xor_sync(0xFFFFFFFFu, s, o);
        float inv = 1.0f / s;
        float w0 = e0*inv, w1 = e1*inv, w2 = e2*inv, w3 = e3*inv;
        g_attw[b*128 + lane]      = w0;  out[(size_t)B_*V_ + b*128 + lane]      = w0;
        g_attw[b*128 + 32 + lane] = w1;  out[(size_t)B_*V_ + b*128 + 32 + lane] = w1;
        g_attw[b*128 + 64 + lane] = w2;  out[(size_t)B_*V_ + b*128 + 64 + lane] = w2;
        g_attw[b*128 + 96 + lane] = w3;  out[(size_t)B_*V_ + b*128 + 96 + lane] = w3;
    }
    gsync();

    // ---- S6: context ----
    if (gtid < 32768){
        int b = gtid >> 10, e = gtid & 1023;
        const float* ep = enc + (size_t)b*1024 + e;
        const float* wsp = g_attw + b*128;
        float a = 0.0f;
        #pragma unroll 16
        for (int s = 0; s < 128; s++) a += wsp[s] * ep[(size_t)s*32768];
        g_ctx[e*32 + b] = a;
    }
    gsync();

    // ---- S7: comb gemm -> RED into g_outU (pre-initialized with bcomb) ----
    if (bid < 128){
        int kc = bid >> 3, rc = bid & 7;
        int k0 = kc * 128;
        if (kc < 8){
            for (int idx = tid; idx < 128*32; idx += NT){
                int b = idx >> 7, kk = idx & 127;
                smU[kk*USTRIDE + b] = x[b*1024 + k0 + kk];
            }
        } else {
            for (int idx = tid; idx < 128*32; idx += NT){
                int kk = idx >> 5, b = idx & 31;
                smU[kk*USTRIDE + b] = g_ctx[(k0 - 1024 + kk)*32 + b];
            }
        }
        __syncthreads();
        if (wid < 8){
            int urow0 = rc*128 + wid*16;
            int row0 = urow0 + rg*4;
            const float4* w0 = (const float4*)(Wcomb + (size_t)(row0+0)*2048 + k0) + par;
            const float4* w1 = (const float4*)(Wcomb + (size_t)(row0+1)*2048 + k0) + par;
            const float4* w2 = (const float4*)(Wcomb + (size_t)(row0+2)*2048 + k0) + par;
            const float4* w3 = (const float4*)(Wcomb + (size_t)(row0+3)*2048 + k0) + par;
            u64 acc[16];
            #pragma unroll
            for (int p = 0; p < 16; p++) acc[p] = 0;
            float4 a0 = w0[0], a1 = w1[0], a2 = w2[0], a3 = w3[0];
            #pragma unroll
            for (int j = 0; j < 16; j++){
                float4 c0 = a0, c1 = a1, c2 = a2, c3 = a3;
                if (j + 1 < 16){
                    a0 = w0[2*(j+1)]; a1 = w1[2*(j+1)];
                    a2 = w2[2*(j+1)]; a3 = w3[2*(j+1)];
                }
                rb_j(c0, c1, c2, c3, smU + ((2*j+par)*4)*USTRIDE + bq*8, acc);
            }
            rb_stage(stW, acc, rg, bq, par);
            #pragma unroll
            for (int r2 = 0; r2 < 16; r2++){
                float v = stW[r2*34 + lane] + stW[16*34 + r2*34 + lane];
                atomicAdd(&g_outU[(size_t)(urow0 + r2)*32 + lane], v);
            }
            __syncwarp();
        }
    }
    gsync();

    // ---- S9: W_out gemm via mma.sync + fused exp-sum epilogue ----
    {
        uint4* Bs = (uint4*)smU;   // [ks*4 + g][lane] (128KB)
        for (int idx = tid; idx < 4096; idx += NT){
            int l = idx & 31, rest = idx >> 5;
            int ks = rest >> 1, reg = rest & 1;
            int kb = ks*16 + (l&3)*2 + reg*8;
            int nb = l >> 2;
            uint4 hv, lv; unsigned h, lo;
            split2(g_outU[kb*32 + nb],      g_outU[(kb+1)*32 + nb],      h, lo); hv.x = h; lv.x = lo;
            split2(g_outU[kb*32 + nb + 8],  g_outU[(kb+1)*32 + nb + 8],  h, lo); hv.y = h; lv.y = lo;
            split2(g_outU[kb*32 + nb + 16], g_outU[(kb+1)*32 + nb + 16], h, lo); hv.z = h; lv.z = lo;
            split2(g_outU[kb*32 + nb + 24], g_outU[(kb+1)*32 + nb + 24], h, lo); hv.w = h; lv.w = lo;
            Bs[(ks*4 + reg)*32 + l]     = hv;
            Bs[(ks*4 + 2 + reg)*32 + l] = lv;
        }
        if (tid < 32) smT[tid] = 0.0f;     // per-block exp-sum accumulator
        __syncthreads();

        for (int wu = gws; wu < 2000; wu += NB*16){
            int v0 = wu * 16;
            int r = lane >> 2, c = (lane & 3) * 2;
            const float* p0 = Wout + (size_t)(v0 + r)*1024 + c;
            const float* p1 = Wout + (size_t)(v0 + r + 8)*1024 + c;
            float acc[4][4];
            #pragma unroll
            for (int nt = 0; nt < 4; nt++)
                #pragma unroll
                for (int i = 0; i < 4; i++) acc[nt][i] = 0.0f;

            float2 fA[4][4];                 // depth-4 prefetch ring
            #pragma unroll
            for (int s = 0; s < 4; s++){
                const float* q0 = p0 + s*16;
                const float* q1 = p1 + s*16;
                fA[s][0] = *(const float2*)(q0);
                fA[s][1] = *(const float2*)(q1);
                fA[s][2] = *(const float2*)(q0 + 8);
                fA[s][3] = *(const float2*)(q1 + 8);
            }

            #pragma unroll 4
            for (int ks = 0; ks < 64; ks++){
                int sl = ks & 3;
                float2 g0 = fA[sl][0], g1 = fA[sl][1], g2 = fA[sl][2], g3 = fA[sl][3];
                if (ks + 4 < 64){
                    const float* q0 = p0 + (ks+4)*16;
                    const float* q1 = p1 + (ks+4)*16;
                    fA[sl][0] = *(const float2*)(q0);
                    fA[sl][1] = *(const float2*)(q1);
                    fA[sl][2] = *(const float2*)(q0 + 8);
                    fA[sl][3] = *(const float2*)(q1 + 8);
                }
                unsigned ah[4], al[4];
                split2(g0.x, g0.y, ah[0], al[0]);
                split2(g1.x, g1.y, ah[1], al[1]);
                split2(g2.x, g2.y, ah[2], al[2]);
                split2(g3.x, g3.y, ah[3], al[3]);
                uint4* Bsl = (uint4*)smU;
                {
                    uint4 bh0 = Bsl[(ks*4+0)*32 + lane];
                    uint4 bh1 = Bsl[(ks*4+1)*32 + lane];
                    MMA16816(acc[0], ah, bh0.x, bh1.x);
                    MMA16816(acc[0], al, bh0.x, bh1.x);
                    MMA16816(acc[1], ah, bh0.y, bh1.y);
                    MMA16816(acc[1], al, bh0.y, bh1.y);
                    MMA16816(acc[2], ah, bh0.z, bh1.z);
                    MMA16816(acc[2], al, bh0.z, bh1.z);
                    MMA16816(acc[3], ah, bh0.w, bh1.w);
                    MMA16816(acc[3], al, bh0.w, bh1.w);
                }
                {
                    uint4 bl0 = Bsl[(ks*4+2)*32 + lane];
                    uint4 bl1 = Bsl[(ks*4+3)*32 + lane];
                    MMA16816(acc[0], ah, bl0.x, bl1.x);
                    MMA16816(acc[1], ah, bl0.y, bl1.y);
                    MMA16816(acc[2], ah, bl0.z, bl1.z);
                    MMA16816(acc[3], ah, bl0.w, bl1.w);
                }
            }

            float bb0 = bout[v0 + r], bb1 = bout[v0 + r + 8];
            float pb0[4], pb1[4];
            #pragma unroll
            for (int nt = 0; nt < 4; nt++){
                int jg = nt*8 + c;
                float x0 = acc[nt][0] + bb0;
                float x1 = acc[nt][1] + bb0;
                float x2 = acc[nt][2] + bb1;
                float x3 = acc[nt][3] + bb1;
                g_logits[(size_t)jg*V_     + v0 + r]     = x0;
                g_logits[(size_t)(jg+1)*V_ + v0 + r]     = x1;
                g_logits[(size_t)jg*V_     + v0 + r + 8] = x2;
                g_logits[(size_t)(jg+1)*V_ + v0 + r + 8] = x3;
                pb0[nt] = __expf(x0) + __expf(x2);   // b = jg
                pb1[nt] = __expf(x1) + __expf(x3);   // b = jg+1
            }
            #pragma unroll
            for (int o = 4; o <= 16; o <<= 1){
                #pragma unroll
                for (int nt = 0; nt < 4; nt++){
                    pb0[nt] += __shfl_xor_sync(0xFFFFFFFFu, pb0[nt], o);
                    pb1[nt] += __shfl_xor_sync(0xFFFFFFFFu, pb1[nt], o);
                }
            }
            if (lane < 4){
                #pragma unroll
                for (int nt = 0; nt < 4; nt++){
                    atomicAdd(&smT[nt*8 + c],     pb0[nt]);
                    atomicAdd(&smT[nt*8 + c + 1], pb1[nt]);
                }
            }
        }
        __syncthreads();
        if (tid < 32) atomicAdd(&g_psb[tid], smT[tid]);
    }
    gsync();

    // ---- S11+S12: off = log(sum) + final write ----
    if (tid < 32) smU[tid] = logf(g_psb[tid]);
    __syncthreads();
    for (int u = gtid; u < 256000; u += NB*NT){
        int b = u / 8000, r = u - b*8000;
        float4 a = ((const float4*)(g_logits + (size_t)b*V_))[r];
        float off = smU[b];
        ((float4*)(out + (size_t)b*V_))[r] =
            make_float4(a.x-off, a.y-off, a.z-off, a.w-off);
    }
}

// ---------------- launch ----------------
extern "C" void kernel_launch(void* const* d_in, const int* in_sizes, int n_in,
                              void* d_out, int out_size)
{
    const float* x     = (const float*)d_in[0];
    const float* enc   = (const float*)d_in[1];
    const float* hid   = (const float*)d_in[2];
    const float* Wih   = (const float*)d_in[3];
    const float* Whh   = (const float*)d_in[4];
    const float* bih   = (const float*)d_in[5];
    const float* bhh   = (const float*)d_in[6];
    const float* Wattn = (const float*)d_in[7];
    // d_in[8] = b_attn: softmax-invariant, unused
    const float* Wcomb = (const float*)d_in[9];
    const float* bcomb = (const float*)d_in[10];
    const float* Wout  = (const float*)d_in[11];
    const float* bout  = (const float*)d_in[12];
    float* out = (float*)d_out;

    static bool once = false;
    if (!once){
        cudaFuncSetAttribute(k_fused, cudaFuncAttributeMaxDynamicSharedMemorySize, SMEM_BYTES);
        once = true;
    }
    k_fused<<<NB, NT, SMEM_BYTES>>>(x, enc, hid, Wih, Whh, bih, bhh,
                                    Wattn, Wcomb, bcomb, Wout, bout, out);
}

// round 15
// speedup vs baseline: 1.1995x; 1.0034x over previous
#include <cuda_runtime.h>
#include <math.h>

#define B_ 32
#define S_ 128
#define V_ 32000
#define NB 148
#define NT 512
#define USTRIDE 36
#define SMU_FLOATS (1024*USTRIDE)
#define SMT_WARP   (2*16*34)
#define SMEM_BYTES ((SMU_FLOATS + 16*SMT_WARP)*4)   // 217088

typedef unsigned long long u64;

// ---------------- scratch ----------------
__device__ __align__(16) float g_gx[3072*32];         // x-gate accumulator [row][b]
__device__ __align__(16) float g_gh[3072*32];         // h-gate accumulator [row][b]
__device__ __align__(16) float g_v[32*1024];          // [b][e] (atomic-accumulated)
__device__ __align__(16) float g_attw[32*128];
__device__ __align__(16) float g_ctx[1024*32];        // [e][b] (atomic-accumulated)
__device__ __align__(16) float g_outU[1024*32];       // [k][b] (init=bcomb, atomic-accumulated)
__device__ __align__(16) float g_logits[32*32000];    // [b][v]
__device__ float g_psb[32];                           // per-b exp-sum (atomic)

// ---------------- grid barrier ----------------
__device__ unsigned g_bar_cnt;
__device__ volatile unsigned g_bar_gen;

__device__ __forceinline__ void gsync(){
    __syncthreads();
    if (threadIdx.x == 0){
        unsigned target = g_bar_gen + 1u;
        __threadfence();
        if (atomicAdd(&g_bar_cnt, 1u) == NB - 1u){
            g_bar_cnt = 0u;
            __threadfence();
            g_bar_gen = target;
        } else {
            while ((int)(g_bar_gen - target) < 0) __nanosleep(64);
            __threadfence();
        }
    }
    __syncthreads();
}

// ---------------- f32x2 helpers ----------------
#define FMA2(acc,a,b) asm("fma.rn.f32x2 %0, %1, %2, %0;" : "+l"(acc) : "l"(a), "l"(b))
__device__ __forceinline__ u64 dup2(float w){ u64 r; asm("mov.b64 %0, {%1, %1};" : "=l"(r) : "f"(w)); return r; }
__device__ __forceinline__ u64 d2u(double d){ return (u64)__double_as_longlong(d); }
__device__ __forceinline__ void unpk(u64 v, float& a, float& b){ asm("mov.b64 {%0,%1}, %2;" : "=f"(a), "=f"(b) : "l"(v)); }
#define PREF_L2(p) asm volatile("prefetch.global.L2 [%0];" :: "l"(p))

__device__ __forceinline__ void rb_k(float w0, float w1, float w2, float w3,
                                     const float* Ub, u64 acc[16]){
    double2 ua = *(const double2*)(Ub);
    double2 ub = *(const double2*)(Ub + 4);
    u64 u0 = d2u(ua.x), u1 = d2u(ua.y), u2 = d2u(ub.x), u3 = d2u(ub.y);
    u64 d0 = dup2(w0), d1 = dup2(w1), d2 = dup2(w2), d3 = dup2(w3);
    FMA2(acc[0],  d0, u0); FMA2(acc[1],  d0, u1); FMA2(acc[2],  d0, u2); FMA2(acc[3],  d0, u3);
    FMA2(acc[4],  d1, u0); FMA2(acc[5],  d1, u1); FMA2(acc[6],  d1, u2); FMA2(acc[7],  d1, u3);
    FMA2(acc[8],  d2, u0); FMA2(acc[9],  d2, u1); FMA2(acc[10], d2, u2); FMA2(acc[11], d2, u3);
    FMA2(acc[12], d3, u0); FMA2(acc[13], d3, u1); FMA2(acc[14], d3, u2); FMA2(acc[15], d3, u3);
}

__device__ __forceinline__ void rb_j(float4 c0, float4 c1, float4 c2, float4 c3,
                                     const float* Ub, u64 acc[16]){
    rb_k(c0.x, c1.x, c2.x, c3.x, Ub,             acc);
    rb_k(c0.y, c1.y, c2.y, c3.y, Ub + USTRIDE,   acc);
    rb_k(c0.z, c1.z, c2.z, c3.z, Ub + 2*USTRIDE, acc);
    rb_k(c0.w, c1.w, c2.w, c3.w, Ub + 3*USTRIDE, acc);
}

__device__ __forceinline__ void rb_stage(float* st, const u64 acc[16], int rg, int bq, int par){
    float* s = st + par*(16*34);
    #pragma unroll
    for (int i = 0; i < 4; i++){
        #pragma unroll
        for (int p = 0; p < 4; p++){
            float lo, hi; unpk(acc[i*4+p], lo, hi);
            *(float2*)(s + (rg*4+i)*34 + bq*8 + 2*p) = make_float2(lo, hi);
        }
    }
    __syncwarp();
}

// comb GEMM block: 16 k-float4s per row group, rows i0..i0+127, RED to g_outU
__device__ __forceinline__ void comb_block(const float* __restrict__ Wcomb, const float* smU,
                                           float* stW, int i0, int kofs,
                                           int wid, int lane, int rg, int bq, int par){
    if (wid < 8){
        int urow0 = i0 + wid*16;
        int row0 = urow0 + rg*4;
        const float4* w0 = (const float4*)(Wcomb + (size_t)(row0+0)*2048 + kofs) + par;
        const float4* w1 = (const float4*)(Wcomb + (size_t)(row0+1)*2048 + kofs) + par;
        const float4* w2 = (const float4*)(Wcomb + (size_t)(row0+2)*2048 + kofs) + par;
        const float4* w3 = (const float4*)(Wcomb + (size_t)(row0+3)*2048 + kofs) + par;
        u64 acc[16];
        #pragma unroll
        for (int p = 0; p < 16; p++) acc[p] = 0;
        float4 a0 = w0[0], a1 = w1[0], a2 = w2[0], a3 = w3[0];
        #pragma unroll
        for (int j = 0; j < 16; j++){
            float4 c0 = a0, c1 = a1, c2 = a2, c3 = a3;
            if (j + 1 < 16){
                a0 = w0[2*(j+1)]; a1 = w1[2*(j+1)];
                a2 = w2[2*(j+1)]; a3 = w3[2*(j+1)];
            }
            rb_j(c0, c1, c2, c3, smU + ((2*j+par)*4)*USTRIDE + bq*8, acc);
        }
        rb_stage(stW, acc, rg, bq, par);
        #pragma unroll
        for (int r2 = 0; r2 < 16; r2++){
            float v = stW[r2*34 + lane] + stW[16*34 + r2*34 + lane];
            atomicAdd(&g_outU[(size_t)(urow0 + r2)*32 + lane], v);
        }
        __syncwarp();
    }
}

// split fp32 -> bf16 hi (truncate) pair + bf16 lo (rounded residual) pair
__device__ __forceinline__ void split2(float w0, float w1, unsigned& h2, unsigned& l2){
    unsigned u0 = __float_as_uint(w0), u1 = __float_as_uint(w1);
    h2 = __byte_perm(u0, u1, 0x7632);
    float l0 = w0 - __uint_as_float(u0 & 0xFFFF0000u);
    float l1 = w1 - __uint_as_float(u1 & 0xFFFF0000u);
    asm("cvt.rn.bf16x2.f32 %0, %1, %2;" : "=r"(l2) : "f"(l1), "f"(l0));
}

// m16n8k16 bf16 mma, f32 accumulate (base-arch instruction, sm_80+)
#define MMA16816(c, a, b0r, b1r) \
    asm volatile("mma.sync.aligned.m16n8k16.row.col.f32.bf16.bf16.f32 " \
        "{%0,%1,%2,%3}, {%4,%5,%6,%7}, {%8,%9}, {%0,%1,%2,%3};" \
        : "+f"((c)[0]), "+f"((c)[1]), "+f"((c)[2]), "+f"((c)[3]) \
        : "r"((a)[0]), "r"((a)[1]), "r"((a)[2]), "r"((a)[3]), "r"(b0r), "r"(b1r))

// ================= fused kernel =================
__global__ void __launch_bounds__(NT, 1) k_fused(
    const float* __restrict__ x, const float* __restrict__ enc,
    const float* __restrict__ hid,
    const float* __restrict__ Wih, const float* __restrict__ Whh,
    const float* __restrict__ bih, const float* __restrict__ bhh,
    const float* __restrict__ Wattn,
    const float* __restrict__ Wcomb, const float* __restrict__ bcomb,
    const float* __restrict__ Wout, const float* __restrict__ bout,
    float* __restrict__ out)
{
    extern __shared__ float smU[];
    float* smT = smU + SMU_FLOATS;
    const int bid = blockIdx.x, tid = threadIdx.x;
    const int wid = tid >> 5, lane = tid & 31;
    const int gtid = bid * NT + tid;
    const int gws = wid * NB + bid;     // block-balanced warp unit id
    const int rg  = lane >> 3;
    const int bq  = (lane >> 1) & 3;
    const int par = lane & 1;
    float* stW = smT + wid * SMT_WARP;

    // ---- Sinit: zero accumulators; init g_outU = bcomb; prefetch GRU weights (24MB) ----
    for (int u = gtid; u < 3072*32; u += NB*NT){ g_gx[u] = 0.0f; g_gh[u] = 0.0f; }
    for (int u = gtid; u < 32768; u += NB*NT){
        g_v[u] = 0.0f;
        g_ctx[u] = 0.0f;
        g_outU[u] = bcomb[u >> 5];
    }
    if (gtid < 32) g_psb[gtid] = 0.0f;
    for (int L = gtid; L < 98304; L += NB*NT){
        PREF_L2(Wih + (size_t)L*32);
        PREF_L2(Whh + (size_t)L*32);
    }
    gsync();

    // ---- S0: GRU gemm partials -> RED into g_gx / g_gh; idle blocks prefetch enc ----
    if (bid < 128){
        int mat = bid >> 6, r = bid & 63;
        int kc = r >> 4, vb = r & 15;
        const float* W   = mat ? Whh : Wih;
        const float* src = mat ? hid : x;
        int k0 = kc * 256;
        for (int idx = tid; idx < 256*32; idx += NT){
            int b = idx >> 8, kk = idx & 255;
            smU[kk*USTRIDE + b] = src[b*1024 + k0 + kk];
        }
        __syncthreads();
        if (wid < 12){
            int urow0 = vb*192 + wid*16;
            int row0 = urow0 + rg*4;
            const float4* w0 = (const float4*)(W + (size_t)(row0+0)*1024 + k0) + par;
            const float4* w1 = (const float4*)(W + (size_t)(row0+1)*1024 + k0) + par;
            const float4* w2 = (const float4*)(W + (size_t)(row0+2)*1024 + k0) + par;
            const float4* w3 = (const float4*)(W + (size_t)(row0+3)*1024 + k0) + par;
            u64 acc[16];
            #pragma unroll
            for (int p = 0; p < 16; p++) acc[p] = 0;
            float4 a0 = w0[0], a1 = w1[0], a2 = w2[0], a3 = w3[0];
            for (int j = 0; j < 32; j++){
                float4 c0 = a0, c1 = a1, c2 = a2, c3 = a3;
                if (j + 1 < 32){
                    a0 = w0[2*(j+1)]; a1 = w1[2*(j+1)];
                    a2 = w2[2*(j+1)]; a3 = w3[2*(j+1)];
                }
                rb_j(c0, c1, c2, c3, smU + ((2*j+par)*4)*USTRIDE + bq*8, acc);
            }
            rb_stage(stW, acc, rg, bq, par);
            float* P = mat ? g_gh : g_gx;
            #pragma unroll
            for (int r2 = 0; r2 < 16; r2++){
                float v = stW[r2*34 + lane] + stW[16*34 + r2*34 + lane];
                atomicAdd(&P[(size_t)(urow0 + r2)*32 + lane], v);
            }
            __syncwarp();
        }
    } else {
        // blocks 128-147: prefetch enc (16MB)
        for (int L = (bid - 128)*NT + tid; L < 131072; L += 20*NT)
            PREF_L2(enc + (size_t)L*32);
    }
    gsync();

    // ---- S2: v gemm (GRU activation fused into staging) -> RED into g_v[b][e] ----
    if (bid < 128){
        int kc = bid >> 2, e0 = (bid & 3) * 256;
        int k0 = kc * 32;
        for (int idx = tid; idx < 1024; idx += NT){
            int k = idx >> 5, b = idx & 31;
            int h = k0 + k;
            float xr = g_gx[(size_t)h*32+b]          + bih[h];
            float xz = g_gx[(size_t)(1024+h)*32+b]   + bih[1024+h];
            float xn = g_gx[(size_t)(2048+h)*32+b]   + bih[2048+h];
            float hr = g_gh[(size_t)h*32+b]          + bhh[h];
            float hz = g_gh[(size_t)(1024+h)*32+b]   + bhh[1024+h];
            float hn = g_gh[(size_t)(2048+h)*32+b]   + bhh[2048+h];
            float rr = 1.0f/(1.0f+expf(-(xr+hr)));
            float zz = 1.0f/(1.0f+expf(-(xz+hz)));
            float nn = tanhf(xn + rr*hn);
            smU[k*USTRIDE + b] = (1.0f-zz)*nn + zz*hid[b*1024+h];
        }
        __syncthreads();
        if (tid < 256){
            int e = e0 + tid;
            const float* wp = Wattn + (size_t)k0*2048 + 1024 + e;
            u64 acc[16];
            #pragma unroll
            for (int p = 0; p < 16; p++) acc[p] = 0;
            #pragma unroll 8
            for (int k = 0; k < 32; k++){
                u64 wd = dup2(wp[(size_t)k*2048]);
                #pragma unroll
                for (int p = 0; p < 16; p += 2){
                    double2 u2 = *(const double2*)(smU + k*USTRIDE + 2*p);
                    FMA2(acc[p],   wd, d2u(u2.x));
                    FMA2(acc[p+1], wd, d2u(u2.y));
                }
            }
            #pragma unroll
            for (int p = 0; p < 16; p++){
                float lo, hi; unpk(acc[p], lo, hi);
                atomicAdd(&g_v[(size_t)(2*p  )*1024 + e], lo);
                atomicAdd(&g_v[(size_t)(2*p+1)*1024 + e], hi);
            }
        }
    } else {
        // blocks 128-147: prefetch Wcomb (8MB)
        for (int L = (bid - 128)*NT + tid; L < 65536; L += 20*NT)
            PREF_L2(Wcomb + (size_t)L*32);
    }
    gsync();

    // ---- S45: scores + softmax (blocks 0-31); comb x-half GEMM (blocks 32-95) ----
    if (bid < 32){
        int b = bid;
        #pragma unroll
        for (int q = 0; q < 8; q++){
            int s = wid*8 + q;
            const float4* ep = (const float4*)(enc + (size_t)(s*32+b)*1024);
            const float4* vp = (const float4*)(g_v + b*1024);
            float a = 0.0f;
            #pragma unroll
            for (int i = 0; i < 8; i++){
                float4 e4 = ep[i*32 + lane];
                float4 v4 = vp[i*32 + lane];
                a += e4.x*v4.x + e4.y*v4.y + e4.z*v4.z + e4.w*v4.w;
            }
            #pragma unroll
            for (int o = 16; o; o >>= 1) a += __shfl_xor_sync(0xFFFFFFFFu, a, o);
            if (lane == 0) smU[s] = a;
        }
        __syncthreads();
        if (wid == 0){
            float v0 = smU[lane], v1 = smU[32+lane], v2 = smU[64+lane], v3 = smU[96+lane];
            float m = fmaxf(fmaxf(v0,v1), fmaxf(v2,v3));
            #pragma unroll
            for (int o = 16; o; o >>= 1) m = fmaxf(m, __shfl_xor_sync(0xFFFFFFFFu, m, o));
            float e0 = expf(v0-m), e1 = expf(v1-m), e2 = expf(v2-m), e3 = expf(v3-m);
            float s = e0+e1+e2+e3;
            #pragma unroll
            for (int o = 16; o; o >>= 1) s += __shfl_xor_sync(0xFFFFFFFFu, s, o);
            float inv = 1.0f / s;
            float w0 = e0*inv, w1 = e1*inv, w2 = e2*inv, w3 = e3*inv;
            g_attw[b*128 + lane]      = w0;  out[(size_t)B_*V_ + b*128 + lane]      = w0;
            g_attw[b*128 + 32 + lane] = w1;  out[(size_t)B_*V_ + b*128 + 32 + lane] = w1;
            g_attw[b*128 + 64 + lane] = w2;  out[(size_t)B_*V_ + b*128 + 64 + lane] = w2;
            g_attw[b*128 + 96 + lane] = w3;  out[(size_t)B_*V_ + b*128 + 96 + lane] = w3;
        }
    } else if (bid < 96){
        int b2 = bid - 32;
        int kc = b2 >> 3, rc = b2 & 7;
        int k0 = kc * 128;
        for (int idx = tid; idx < 128*32; idx += NT){
            int b = idx >> 7, kk = idx & 127;
            smU[kk*USTRIDE + b] = x[b*1024 + k0 + kk];
        }
        __syncthreads();
        comb_block(Wcomb, smU, stW, rc*128, k0, wid, lane, rg, bq, par);
    }
    gsync();

    // ---- S6: context (balanced warp units, s-split, RED into g_ctx) ----
    if (gws < 2048){
        int b = gws >> 6, ec = (gws >> 1) & 31, sh = gws & 1;
        int e = ec*32 + lane;
        const float* ep = enc + (size_t)(sh*64)*32768 + (size_t)b*1024 + e;
        const float* wsp = g_attw + b*128 + sh*64;
        float a = 0.0f;
        #pragma unroll 16
        for (int s = 0; s < 64; s++) a += wsp[s] * ep[(size_t)s*32768];
        atomicAdd(&g_ctx[e*32 + b], a);
    }
    gsync();

    // ---- S7: comb ctx-half GEMM (64 blocks) -> RED into g_outU ----
    if (bid < 64){
        int kc8 = bid >> 3, rc = bid & 7;
        int k0c = kc8 * 128;
        for (int idx = tid; idx < 128*32; idx += NT){
            int kk = idx >> 5, b = idx & 31;
            smU[kk*USTRIDE + b] = g_ctx[(k0c + kk)*32 + b];
        }
        __syncthreads();
        comb_block(Wcomb, smU, stW, rc*128, 1024 + k0c, wid, lane, rg, bq, par);
    }
    gsync();

    // ---- S9: W_out gemm via mma.sync + fused exp-sum epilogue ----
    {
        uint4* Bs = (uint4*)smU;   // [ks*4 + g][lane] (128KB)
        for (int idx = tid; idx < 4096; idx += NT){
            int l = idx & 31, rest = idx >> 5;
            int ks = rest >> 1, reg = rest & 1;
            int kb = ks*16 + (l&3)*2 + reg*8;
            int nb = l >> 2;
            uint4 hv, lv; unsigned h, lo;
            split2(g_outU[kb*32 + nb],      g_outU[(kb+1)*32 + nb],      h, lo); hv.x = h; lv.x = lo;
            split2(g_outU[kb*32 + nb + 8],  g_outU[(kb+1)*32 + nb + 8],  h, lo); hv.y = h; lv.y = lo;
            split2(g_outU[kb*32 + nb + 16], g_outU[(kb+1)*32 + nb + 16], h, lo); hv.z = h; lv.z = lo;
            split2(g_outU[kb*32 + nb + 24], g_outU[(kb+1)*32 + nb + 24], h, lo); hv.w = h; lv.w = lo;
            Bs[(ks*4 + reg)*32 + l]     = hv;
            Bs[(ks*4 + 2 + reg)*32 + l] = lv;
        }
        if (tid < 32) smT[tid] = 0.0f;     // per-block exp-sum accumulator
        __syncthreads();

        for (int wu = gws; wu < 2000; wu += NB*16){
            int v0 = wu * 16;
            int r = lane >> 2, c = (lane & 3) * 2;
            const float* p0 = Wout + (size_t)(v0 + r)*1024 + c;
            const float* p1 = Wout + (size_t)(v0 + r + 8)*1024 + c;
            float acc[4][4];
            #pragma unroll
            for (int nt = 0; nt < 4; nt++)
                #pragma unroll
                for (int i = 0; i < 4; i++) acc[nt][i] = 0.0f;

            float2 fA[4][4];                 // depth-4 prefetch ring
            #pragma unroll
            for (int s = 0; s < 4; s++){
                const float* q0 = p0 + s*16;
                const float* q1 = p1 + s*16;
                fA[s][0] = *(const float2*)(q0);
                fA[s][1] = *(const float2*)(q1);
                fA[s][2] = *(const float2*)(q0 + 8);
                fA[s][3] = *(const float2*)(q1 + 8);
            }

            #pragma unroll 4
            for (int ks = 0; ks < 64; ks++){
                int sl = ks & 3;
                float2 g0 = fA[sl][0], g1 = fA[sl][1], g2 = fA[sl][2], g3 = fA[sl][3];
                if (ks + 4 < 64){
                    const float* q0 = p0 + (ks+4)*16;
                    const float* q1 = p1 + (ks+4)*16;
                    fA[sl][0] = *(const float2*)(q0);
                    fA[sl][1] = *(const float2*)(q1);
                    fA[sl][2] = *(const float2*)(q0 + 8);
                    fA[sl][3] = *(const float2*)(q1 + 8);
                }
                unsigned ah[4], al[4];
                split2(g0.x, g0.y, ah[0], al[0]);
                split2(g1.x, g1.y, ah[1], al[1]);
                split2(g2.x, g2.y, ah[2], al[2]);
                split2(g3.x, g3.y, ah[3], al[3]);
                uint4* Bsl = (uint4*)smU;
                {
                    uint4 bh0 = Bsl[(ks*4+0)*32 + lane];
                    uint4 bh1 = Bsl[(ks*4+1)*32 + lane];
                    MMA16816(acc[0], ah, bh0.x, bh1.x);
                    MMA16816(acc[0], al, bh0.x, bh1.x);
                    MMA16816(acc[1], ah, bh0.y, bh1.y);
                    MMA16816(acc[1], al, bh0.y, bh1.y);
                    MMA16816(acc[2], ah, bh0.z, bh1.z);
                    MMA16816(acc[2], al, bh0.z, bh1.z);
                    MMA16816(acc[3], ah, bh0.w, bh1.w);
                    MMA16816(acc[3], al, bh0.w, bh1.w);
                }
                {
                    uint4 bl0 = Bsl[(ks*4+2)*32 + lane];
                    uint4 bl1 = Bsl[(ks*4+3)*32 + lane];
                    MMA16816(acc[0], ah, bl0.x, bl1.x);
                    MMA16816(acc[1], ah, bl0.y, bl1.y);
                    MMA16816(acc[2], ah, bl0.z, bl1.z);
                    MMA16816(acc[3], ah, bl0.w, bl1.w);
                }
            }

            float bb0 = bout[v0 + r], bb1 = bout[v0 + r + 8];
            float pb0[4], pb1[4];
            #pragma unroll
            for (int nt = 0; nt < 4; nt++){
                int jg = nt*8 + c;
                float x0 = acc[nt][0] + bb0;
                float x1 = acc[nt][1] + bb0;
                float x2 = acc[nt][2] + bb1;
                float x3 = acc[nt][3] + bb1;
                g_logits[(size_t)jg*V_     + v0 + r]     = x0;
                g_logits[(size_t)(jg+1)*V_ + v0 + r]     = x1;
                g_logits[(size_t)jg*V_     + v0 + r + 8] = x2;
                g_logits[(size_t)(jg+1)*V_ + v0 + r + 8] = x3;
                pb0[nt] = __expf(x0) + __expf(x2);   // b = jg
                pb1[nt] = __expf(x1) + __expf(x3);   // b = jg+1
            }
            #pragma unroll
            for (int o = 4; o <= 16; o <<= 1){
                #pragma unroll
                for (int nt = 0; nt < 4; nt++){
                    pb0[nt] += __shfl_xor_sync(0xFFFFFFFFu, pb0[nt], o);
                    pb1[nt] += __shfl_xor_sync(0xFFFFFFFFu, pb1[nt], o);
                }
            }
            if (lane < 4){
                #pragma unroll
                for (int nt = 0; nt < 4; nt++){
                    atomicAdd(&smT[nt*8 + c],     pb0[nt]);
                    atomicAdd(&smT[nt*8 + c + 1], pb1[nt]);
                }
            }
        }
        __syncthreads();
        if (tid < 32) atomicAdd(&g_psb[tid], smT[tid]);
    }
    gsync();

    // ---- S11+S12: off = log(sum) + final write ----
    if (tid < 32) smU[tid] = logf(g_psb[tid]);
    __syncthreads();
    for (int u = gtid; u < 256000; u += NB*NT){
        int b = u / 8000, r = u - b*8000;
        float4 a = ((const float4*)(g_logits + (size_t)b*V_))[r];
        float off = smU[b];
        ((float4*)(out + (size_t)b*V_))[r] =
            make_float4(a.x-off, a.y-off, a.z-off, a.w-off);
    }
}

// ---------------- launch ----------------
extern "C" void kernel_launch(void* const* d_in, const int* in_sizes, int n_in,
                              void* d_out, int out_size)
{
    const float* x     = (const float*)d_in[0];
    const float* enc   = (const float*)d_in[1];
    const float* hid   = (const float*)d_in[2];
    const float* Wih   = (const float*)d_in[3];
    const float* Whh   = (const float*)d_in[4];
    const float* bih   = (const float*)d_in[5];
    const float* bhh   = (const float*)d_in[6];
    const float* Wattn = (const float*)d_in[7];
    // d_in[8] = b_attn: softmax-invariant, unused
    const float* Wcomb = (const float*)d_in[9];
    const float* bcomb = (const float*)d_in[10];
    const float* Wout  = (const float*)d_in[11];
    const float* bout  = (const float*)d_in[12];
    float* out = (float*)d_out;

    static bool once = false;
    if (!once){
        cudaFuncSetAttribute(k_fused, cudaFuncAttributeMaxDynamicSharedMemorySize, SMEM_BYTES);
        once = true;
    }
    k_fused<<<NB, NT, SMEM_BYTES>>>(x, enc, hid, Wih, Whh, bih, bhh,
                                    Wattn, Wcomb, bcomb, Wout, bout, out);
}

// round 16
// speedup vs baseline: 1.2175x; 1.0150x over previous
#include <cuda_runtime.h>
#include <math.h>

#define B_ 32
#define S_ 128
#define V_ 32000
#define NB 148
#define NT 512
#define USTRIDE 36
#define SMU_FLOATS (1024*USTRIDE)
#define SMT_WARP   (2*16*34)
#define SMEM_BYTES ((SMU_FLOATS + 16*SMT_WARP)*4)   // 217088

typedef unsigned long long u64;

// ---------------- scratch ----------------
__device__ __align__(16) float g_gx[3072*32];         // x-gate accumulator [row][b]
__device__ __align__(16) float g_gh[3072*32];         // h-gate accumulator [row][b]
__device__ __align__(16) float g_v[32*1024];          // [b][e] (atomic-accumulated)
__device__ __align__(16) float g_ctx[1024*32];        // [e][b] (plain stores, owner-exclusive)
__device__ __align__(16) float g_outU[1024*32];       // [k][b] (init=bcomb, atomic-accumulated)
__device__ __align__(16) float g_logits[32*32000];    // [b][v]
__device__ float g_psb[32];                           // per-b exp-sum (atomic)

// ---------------- grid barrier ----------------
__device__ unsigned g_bar_cnt;
__device__ volatile unsigned g_bar_gen;

__device__ __forceinline__ void gsync(){
    __syncthreads();
    if (threadIdx.x == 0){
        unsigned target = g_bar_gen + 1u;
        __threadfence();
        if (atomicAdd(&g_bar_cnt, 1u) == NB - 1u){
            g_bar_cnt = 0u;
            __threadfence();
            g_bar_gen = target;
        } else {
            while ((int)(g_bar_gen - target) < 0) __nanosleep(64);
            __threadfence();
        }
    }
    __syncthreads();
}

// ---------------- f32x2 helpers ----------------
#define FMA2(acc,a,b) asm("fma.rn.f32x2 %0, %1, %2, %0;" : "+l"(acc) : "l"(a), "l"(b))
__device__ __forceinline__ u64 dup2(float w){ u64 r; asm("mov.b64 %0, {%1, %1};" : "=l"(r) : "f"(w)); return r; }
__device__ __forceinline__ u64 d2u(double d){ return (u64)__double_as_longlong(d); }
__device__ __forceinline__ void unpk(u64 v, float& a, float& b){ asm("mov.b64 {%0,%1}, %2;" : "=f"(a), "=f"(b) : "l"(v)); }
#define PREF_L2(p) asm volatile("prefetch.global.L2 [%0];" :: "l"(p))

__device__ __forceinline__ void rb_k(float w0, float w1, float w2, float w3,
                                     const float* Ub, u64 acc[16]){
    double2 ua = *(const double2*)(Ub);
    double2 ub = *(const double2*)(Ub + 4);
    u64 u0 = d2u(ua.x), u1 = d2u(ua.y), u2 = d2u(ub.x), u3 = d2u(ub.y);
    u64 d0 = dup2(w0), d1 = dup2(w1), d2 = dup2(w2), d3 = dup2(w3);
    FMA2(acc[0],  d0, u0); FMA2(acc[1],  d0, u1); FMA2(acc[2],  d0, u2); FMA2(acc[3],  d0, u3);
    FMA2(acc[4],  d1, u0); FMA2(acc[5],  d1, u1); FMA2(acc[6],  d1, u2); FMA2(acc[7],  d1, u3);
    FMA2(acc[8],  d2, u0); FMA2(acc[9],  d2, u1); FMA2(acc[10], d2, u2); FMA2(acc[11], d2, u3);
    FMA2(acc[12], d3, u0); FMA2(acc[13], d3, u1); FMA2(acc[14], d3, u2); FMA2(acc[15], d3, u3);
}

__device__ __forceinline__ void rb_j(float4 c0, float4 c1, float4 c2, float4 c3,
                                     const float* Ub, u64 acc[16]){
    rb_k(c0.x, c1.x, c2.x, c3.x, Ub,             acc);
    rb_k(c0.y, c1.y, c2.y, c3.y, Ub + USTRIDE,   acc);
    rb_k(c0.z, c1.z, c2.z, c3.z, Ub + 2*USTRIDE, acc);
    rb_k(c0.w, c1.w, c2.w, c3.w, Ub + 3*USTRIDE, acc);
}

__device__ __forceinline__ void rb_stage(float* st, const u64 acc[16], int rg, int bq, int par){
    float* s = st + par*(16*34);
    #pragma unroll
    for (int i = 0; i < 4; i++){
        #pragma unroll
        for (int p = 0; p < 4; p++){
            float lo, hi; unpk(acc[i*4+p], lo, hi);
            *(float2*)(s + (rg*4+i)*34 + bq*8 + 2*p) = make_float2(lo, hi);
        }
    }
    __syncwarp();
}

// comb GEMM block: 16 k-float4s per row group, rows i0..i0+127, RED to g_outU
__device__ __forceinline__ void comb_block(const float* __restrict__ Wcomb, const float* smU,
                                           float* stW, int i0, int kofs,
                                           int wid, int lane, int rg, int bq, int par){
    if (wid < 8){
        int urow0 = i0 + wid*16;
        int row0 = urow0 + rg*4;
        const float4* w0 = (const float4*)(Wcomb + (size_t)(row0+0)*2048 + kofs) + par;
        const float4* w1 = (const float4*)(Wcomb + (size_t)(row0+1)*2048 + kofs) + par;
        const float4* w2 = (const float4*)(Wcomb + (size_t)(row0+2)*2048 + kofs) + par;
        const float4* w3 = (const float4*)(Wcomb + (size_t)(row0+3)*2048 + kofs) + par;
        u64 acc[16];
        #pragma unroll
        for (int p = 0; p < 16; p++) acc[p] = 0;
        float4 a0 = w0[0], a1 = w1[0], a2 = w2[0], a3 = w3[0];
        #pragma unroll
        for (int j = 0; j < 16; j++){
            float4 c0 = a0, c1 = a1, c2 = a2, c3 = a3;
            if (j + 1 < 16){
                a0 = w0[2*(j+1)]; a1 = w1[2*(j+1)];
                a2 = w2[2*(j+1)]; a3 = w3[2*(j+1)];
            }
            rb_j(c0, c1, c2, c3, smU + ((2*j+par)*4)*USTRIDE + bq*8, acc);
        }
        rb_stage(stW, acc, rg, bq, par);
        #pragma unroll
        for (int r2 = 0; r2 < 16; r2++){
            float v = stW[r2*34 + lane] + stW[16*34 + r2*34 + lane];
            atomicAdd(&g_outU[(size_t)(urow0 + r2)*32 + lane], v);
        }
        __syncwarp();
    }
}

// split fp32 -> bf16 hi (truncate) pair + bf16 lo (rounded residual) pair
__device__ __forceinline__ void split2(float w0, float w1, unsigned& h2, unsigned& l2){
    unsigned u0 = __float_as_uint(w0), u1 = __float_as_uint(w1);
    h2 = __byte_perm(u0, u1, 0x7632);
    float l0 = w0 - __uint_as_float(u0 & 0xFFFF0000u);
    float l1 = w1 - __uint_as_float(u1 & 0xFFFF0000u);
    asm("cvt.rn.bf16x2.f32 %0, %1, %2;" : "=r"(l2) : "f"(l1), "f"(l0));
}

// m16n8k16 bf16 mma, f32 accumulate (base-arch instruction, sm_80+)
#define MMA16816(c, a, b0r, b1r) \
    asm volatile("mma.sync.aligned.m16n8k16.row.col.f32.bf16.bf16.f32 " \
        "{%0,%1,%2,%3}, {%4,%5,%6,%7}, {%8,%9}, {%0,%1,%2,%3};" \
        : "+f"((c)[0]), "+f"((c)[1]), "+f"((c)[2]), "+f"((c)[3]) \
        : "r"((a)[0]), "r"((a)[1]), "r"((a)[2]), "r"((a)[3]), "r"(b0r), "r"(b1r))

// ================= fused kernel =================
__global__ void __launch_bounds__(NT, 1) k_fused(
    const float* __restrict__ x, const float* __restrict__ enc,
    const float* __restrict__ hid,
    const float* __restrict__ Wih, const float* __restrict__ Whh,
    const float* __restrict__ bih, const float* __restrict__ bhh,
    const float* __restrict__ Wattn,
    const float* __restrict__ Wcomb, const float* __restrict__ bcomb,
    const float* __restrict__ Wout, const float* __restrict__ bout,
    float* __restrict__ out)
{
    extern __shared__ float smU[];
    float* smT = smU + SMU_FLOATS;
    const int bid = blockIdx.x, tid = threadIdx.x;
    const int wid = tid >> 5, lane = tid & 31;
    const int gtid = bid * NT + tid;
    const int gws = wid * NB + bid;     // block-balanced warp unit id
    const int rg  = lane >> 3;
    const int bq  = (lane >> 1) & 3;
    const int par = lane & 1;
    float* stW = smT + wid * SMT_WARP;

    // ---- Sinit: zero gate accumulators; prefetch GRU weights (24MB, fits L2) ----
    for (int u = gtid; u < 3072*32; u += NB*NT){ g_gx[u] = 0.0f; g_gh[u] = 0.0f; }
    for (int L = gtid; L < 98304; L += NB*NT){
        PREF_L2(Wih + (size_t)L*32);
        PREF_L2(Whh + (size_t)L*32);
    }
    gsync();

    // ---- S0: GRU gemm partials -> RED; idle blocks: enc prefetch + small inits ----
    if (bid < 128){
        int mat = bid >> 6, r = bid & 63;
        int kc = r >> 4, vb = r & 15;
        const float* W   = mat ? Whh : Wih;
        const float* src = mat ? hid : x;
        int k0 = kc * 256;
        for (int idx = tid; idx < 256*32; idx += NT){
            int b = idx >> 8, kk = idx & 255;
            smU[kk*USTRIDE + b] = src[b*1024 + k0 + kk];
        }
        __syncthreads();
        if (wid < 12){
            int urow0 = vb*192 + wid*16;
            int row0 = urow0 + rg*4;
            const float4* w0 = (const float4*)(W + (size_t)(row0+0)*1024 + k0) + par;
            const float4* w1 = (const float4*)(W + (size_t)(row0+1)*1024 + k0) + par;
            const float4* w2 = (const float4*)(W + (size_t)(row0+2)*1024 + k0) + par;
            const float4* w3 = (const float4*)(W + (size_t)(row0+3)*1024 + k0) + par;
            u64 acc[16];
            #pragma unroll
            for (int p = 0; p < 16; p++) acc[p] = 0;
            float4 a0 = w0[0], a1 = w1[0], a2 = w2[0], a3 = w3[0];
            for (int j = 0; j < 32; j++){
                float4 c0 = a0, c1 = a1, c2 = a2, c3 = a3;
                if (j + 1 < 32){
                    a0 = w0[2*(j+1)]; a1 = w1[2*(j+1)];
                    a2 = w2[2*(j+1)]; a3 = w3[2*(j+1)];
                }
                rb_j(c0, c1, c2, c3, smU + ((2*j+par)*4)*USTRIDE + bq*8, acc);
            }
            rb_stage(stW, acc, rg, bq, par);
            float* P = mat ? g_gh : g_gx;
            #pragma unroll
            for (int r2 = 0; r2 < 16; r2++){
                float v = stW[r2*34 + lane] + stW[16*34 + r2*34 + lane];
                atomicAdd(&P[(size_t)(urow0 + r2)*32 + lane], v);
            }
            __syncwarp();
        }
    } else {
        // blocks 128-147: enc prefetch (16MB) + g_v zero + g_outU=bcomb + g_psb zero
        int t0 = (bid - 128)*NT + tid;   // 0..10239
        for (int L = t0; L < 131072; L += 20*NT)
            PREF_L2(enc + (size_t)L*32);
        for (int u = t0; u < 32768; u += 20*NT){
            g_v[u] = 0.0f;
            g_outU[u] = bcomb[u >> 5];
        }
        if (t0 < 32) g_psb[t0] = 0.0f;
    }
    gsync();

    // ---- S2: v gemm (GRU activation fused into staging; all 512 threads, 2 k-halves) ----
    if (bid < 128){
        int kc = bid >> 2, e0 = (bid & 3) * 256;
        int k0 = kc * 32;
        for (int idx = tid; idx < 1024; idx += NT){
            int k = idx >> 5, b = idx & 31;
            int h = k0 + k;
            float xr = g_gx[(size_t)h*32+b]          + bih[h];
            float xz = g_gx[(size_t)(1024+h)*32+b]   + bih[1024+h];
            float xn = g_gx[(size_t)(2048+h)*32+b]   + bih[2048+h];
            float hr = g_gh[(size_t)h*32+b]          + bhh[h];
            float hz = g_gh[(size_t)(1024+h)*32+b]   + bhh[1024+h];
            float hn = g_gh[(size_t)(2048+h)*32+b]   + bhh[2048+h];
            float rr = 1.0f/(1.0f+expf(-(xr+hr)));
            float zz = 1.0f/(1.0f+expf(-(xz+hz)));
            float nn = tanhf(xn + rr*hn);
            smU[k*USTRIDE + b] = (1.0f-zz)*nn + zz*hid[b*1024+h];
        }
        __syncthreads();
        {
            int kh = tid >> 8;               // 0/1: k-half
            int e = e0 + (tid & 255);
            int kb = kh * 16;
            const float* wp = Wattn + (size_t)(k0 + kb)*2048 + 1024 + e;
            u64 acc[16];
            #pragma unroll
            for (int p = 0; p < 16; p++) acc[p] = 0;
            #pragma unroll 8
            for (int k = 0; k < 16; k++){
                u64 wd = dup2(wp[(size_t)k*2048]);
                #pragma unroll
                for (int p = 0; p < 16; p += 2){
                    double2 u2 = *(const double2*)(smU + (kb + k)*USTRIDE + 2*p);
                    FMA2(acc[p],   wd, d2u(u2.x));
                    FMA2(acc[p+1], wd, d2u(u2.y));
                }
            }
            #pragma unroll
            for (int p = 0; p < 16; p++){
                float lo, hi; unpk(acc[p], lo, hi);
                atomicAdd(&g_v[(size_t)(2*p  )*1024 + e], lo);
                atomicAdd(&g_v[(size_t)(2*p+1)*1024 + e], hi);
            }
        }
    } else {
        // blocks 128-147: prefetch Wcomb (8MB)
        for (int L = (bid - 128)*NT + tid; L < 65536; L += 20*NT)
            PREF_L2(Wcomb + (size_t)L*32);
    }
    gsync();

    // ---- S456: blocks 0-31: scores -> softmax -> context (own b); blocks 32-95: comb x-half ----
    if (bid < 32){
        int b = bid;
        #pragma unroll
        for (int q = 0; q < 8; q++){
            int s = wid*8 + q;
            const float4* ep = (const float4*)(enc + (size_t)(s*32+b)*1024);
            const float4* vp = (const float4*)(g_v + b*1024);
            float a = 0.0f;
            #pragma unroll
            for (int i = 0; i < 8; i++){
                float4 e4 = ep[i*32 + lane];
                float4 v4 = vp[i*32 + lane];
                a += e4.x*v4.x + e4.y*v4.y + e4.z*v4.z + e4.w*v4.w;
            }
            #pragma unroll
            for (int o = 16; o; o >>= 1) a += __shfl_xor_sync(0xFFFFFFFFu, a, o);
            if (lane == 0) smU[s] = a;
        }
        __syncthreads();
        if (wid == 0){
            float v0 = smU[lane], v1 = smU[32+lane], v2 = smU[64+lane], v3 = smU[96+lane];
            float m = fmaxf(fmaxf(v0,v1), fmaxf(v2,v3));
            #pragma unroll
            for (int o = 16; o; o >>= 1) m = fmaxf(m, __shfl_xor_sync(0xFFFFFFFFu, m, o));
            float e0 = expf(v0-m), e1 = expf(v1-m), e2 = expf(v2-m), e3 = expf(v3-m);
            float s = e0+e1+e2+e3;
            #pragma unroll
            for (int o = 16; o; o >>= 1) s += __shfl_xor_sync(0xFFFFFFFFu, s, o);
            float inv = 1.0f / s;
            float w0 = e0*inv, w1 = e1*inv, w2 = e2*inv, w3 = e3*inv;
            smU[128 + lane]      = w0;  out[(size_t)B_*V_ + b*128 + lane]      = w0;
            smU[128 + 32 + lane] = w1;  out[(size_t)B_*V_ + b*128 + 32 + lane] = w1;
            smU[128 + 64 + lane] = w2;  out[(size_t)B_*V_ + b*128 + 64 + lane] = w2;
            smU[128 + 96 + lane] = w3;  out[(size_t)B_*V_ + b*128 + 96 + lane] = w3;
        }
        __syncthreads();
        {
            const float* ws = smU + 128;
            int e1i = tid, e2i = tid + 512;
            const float* ep = enc + (size_t)b*1024;
            float a1 = 0.0f, a2 = 0.0f;
            #pragma unroll 16
            for (int s = 0; s < 128; s++){
                float w = ws[s];
                a1 += w * ep[(size_t)s*32768 + e1i];
                a2 += w * ep[(size_t)s*32768 + e2i];
            }
            g_ctx[e1i*32 + b] = a1;
            g_ctx[e2i*32 + b] = a2;
        }
    } else if (bid < 96){
        int b2 = bid - 32;
        int kc = b2 >> 3, rc = b2 & 7;
        int k0 = kc * 128;
        for (int idx = tid; idx < 128*32; idx += NT){
            int b = idx >> 7, kk = idx & 127;
            smU[kk*USTRIDE + b] = x[b*1024 + k0 + kk];
        }
        __syncthreads();
        comb_block(Wcomb, smU, stW, rc*128, k0, wid, lane, rg, bq, par);
    }
    gsync();

    // ---- S7: comb ctx-half GEMM (64 blocks) -> RED into g_outU ----
    if (bid < 64){
        int kc8 = bid >> 3, rc = bid & 7;
        int k0c = kc8 * 128;
        for (int idx = tid; idx < 128*32; idx += NT){
            int kk = idx >> 5, b = idx & 31;
            smU[kk*USTRIDE + b] = g_ctx[(k0c + kk)*32 + b];
        }
        __syncthreads();
        comb_block(Wcomb, smU, stW, rc*128, 1024 + k0c, wid, lane, rg, bq, par);
    }
    gsync();

    // ---- S9: W_out gemm via mma.sync + fused exp-sum epilogue ----
    {
        uint4* Bs = (uint4*)smU;   // [ks*4 + g][lane] (128KB)
        for (int idx = tid; idx < 4096; idx += NT){
            int l = idx & 31, rest = idx >> 5;
            int ks = rest >> 1, reg = rest & 1;
            int kb = ks*16 + (l&3)*2 + reg*8;
            int nb = l >> 2;
            uint4 hv, lv; unsigned h, lo;
            split2(g_outU[kb*32 + nb],      g_outU[(kb+1)*32 + nb],      h, lo); hv.x = h; lv.x = lo;
            split2(g_outU[kb*32 + nb + 8],  g_outU[(kb+1)*32 + nb + 8],  h, lo); hv.y = h; lv.y = lo;
            split2(g_outU[kb*32 + nb + 16], g_outU[(kb+1)*32 + nb + 16], h, lo); hv.z = h; lv.z = lo;
            split2(g_outU[kb*32 + nb + 24], g_outU[(kb+1)*32 + nb + 24], h, lo); hv.w = h; lv.w = lo;
            Bs[(ks*4 + reg)*32 + l]     = hv;
            Bs[(ks*4 + 2 + reg)*32 + l] = lv;
        }
        if (tid < 32) smT[tid] = 0.0f;     // per-block exp-sum accumulator
        __syncthreads();

        for (int wu = gws; wu < 2000; wu += NB*16){
            int v0 = wu * 16;
            int r = lane >> 2, c = (lane & 3) * 2;
            const float* p0 = Wout + (size_t)(v0 + r)*1024 + c;
            const float* p1 = Wout + (size_t)(v0 + r + 8)*1024 + c;
            float acc[4][4];
            #pragma unroll
            for (int nt = 0; nt < 4; nt++)
                #pragma unroll
                for (int i = 0; i < 4; i++) acc[nt][i] = 0.0f;

            float2 fA[4][4];                 // depth-4 prefetch ring
            #pragma unroll
            for (int s = 0; s < 4; s++){
                const float* q0 = p0 + s*16;
                const float* q1 = p1 + s*16;
                fA[s][0] = *(const float2*)(q0);
                fA[s][1] = *(const float2*)(q1);
                fA[s][2] = *(const float2*)(q0 + 8);
                fA[s][3] = *(const float2*)(q1 + 8);
            }

            #pragma unroll 4
            for (int ks = 0; ks < 64; ks++){
                int sl = ks & 3;
                float2 g0 = fA[sl][0], g1 = fA[sl][1], g2 = fA[sl][2], g3 = fA[sl][3];
                if (ks + 4 < 64){
                    const float* q0 = p0 + (ks+4)*16;
                    const float* q1 = p1 + (ks+4)*16;
                    fA[sl][0] = *(const float2*)(q0);
                    fA[sl][1] = *(const float2*)(q1);
                    fA[sl][2] = *(const float2*)(q0 + 8);
                    fA[sl][3] = *(const float2*)(q1 + 8);
                }
                unsigned ah[4], al[4];
                split2(g0.x, g0.y, ah[0], al[0]);
                split2(g1.x, g1.y, ah[1], al[1]);
                split2(g2.x, g2.y, ah[2], al[2]);
                split2(g3.x, g3.y, ah[3], al[3]);
                uint4* Bsl = (uint4*)smU;
                {
                    uint4 bh0 = Bsl[(ks*4+0)*32 + lane];
                    uint4 bh1 = Bsl[(ks*4+1)*32 + lane];
                    MMA16816(acc[0], ah, bh0.x, bh1.x);
                    MMA16816(acc[0], al, bh0.x, bh1.x);
                    MMA16816(acc[1], ah, bh0.y, bh1.y);
                    MMA16816(acc[1], al, bh0.y, bh1.y);
                    MMA16816(acc[2], ah, bh0.z, bh1.z);
                    MMA16816(acc[2], al, bh0.z, bh1.z);
                    MMA16816(acc[3], ah, bh0.w, bh1.w);
                    MMA16816(acc[3], al, bh0.w, bh1.w);
                }
                {
                    uint4 bl0 = Bsl[(ks*4+2)*32 + lane];
                    uint4 bl1 = Bsl[(ks*4+3)*32 + lane];
                    MMA16816(acc[0], ah, bl0.x, bl1.x);
                    MMA16816(acc[1], ah, bl0.y, bl1.y);
                    MMA16816(acc[2], ah, bl0.z, bl1.z);
                    MMA16816(acc[3], ah, bl0.w, bl1.w);
                }
            }

            float bb0 = bout[v0 + r], bb1 = bout[v0 + r + 8];
            float pb0[4], pb1[4];
            #pragma unroll
            for (int nt = 0; nt < 4; nt++){
                int jg = nt*8 + c;
                float x0 = acc[nt][0] + bb0;
                float x1 = acc[nt][1] + bb0;
                float x2 = acc[nt][2] + bb1;
                float x3 = acc[nt][3] + bb1;
                g_logits[(size_t)jg*V_     + v0 + r]     = x0;
                g_logits[(size_t)(jg+1)*V_ + v0 + r]     = x1;
                g_logits[(size_t)jg*V_     + v0 + r + 8] = x2;
                g_logits[(size_t)(jg+1)*V_ + v0 + r + 8] = x3;
                pb0[nt] = __expf(x0) + __expf(x2);   // b = jg
                pb1[nt] = __expf(x1) + __expf(x3);   // b = jg+1
            }
            #pragma unroll
            for (int o = 4; o <= 16; o <<= 1){
                #pragma unroll
                for (int nt = 0; nt < 4; nt++){
                    pb0[nt] += __shfl_xor_sync(0xFFFFFFFFu, pb0[nt], o);
                    pb1[nt] += __shfl_xor_sync(0xFFFFFFFFu, pb1[nt], o);
                }
            }
            if (lane < 4){
                #pragma unroll
                for (int nt = 0; nt < 4; nt++){
                    atomicAdd(&smT[nt*8 + c],     pb0[nt]);
                    atomicAdd(&smT[nt*8 + c + 1], pb1[nt]);
                }
            }
        }
        __syncthreads();
        if (tid < 32) atomicAdd(&g_psb[tid], smT[tid]);
    }
    gsync();

    // ---- S11+S12: off = log(sum) + final write ----
    if (tid < 32) smU[tid] = logf(g_psb[tid]);
    __syncthreads();
    for (int u = gtid; u < 256000; u += NB*NT){
        int b = u / 8000, r = u - b*8000;
        float4 a = ((const float4*)(g_logits + (size_t)b*V_))[r];
        float off = smU[b];
        ((float4*)(out + (size_t)b*V_))[r] =
            make_float4(a.x-off, a.y-off, a.z-off, a.w-off);
    }
}

// ---------------- launch ----------------
extern "C" void kernel_launch(void* const* d_in, const int* in_sizes, int n_in,
                              void* d_out, int out_size)
{
    const float* x     = (const float*)d_in[0];
    const float* enc   = (const float*)d_in[1];
    const float* hid   = (const float*)d_in[2];
    const float* Wih   = (const float*)d_in[3];
    const float* Whh   = (const float*)d_in[4];
    const float* bih   = (const float*)d_in[5];
    const float* bhh   = (const float*)d_in[6];
    const float* Wattn = (const float*)d_in[7];
    // d_in[8] = b_attn: softmax-invariant, unused
    const float* Wcomb = (const float*)d_in[9];
    const float* bcomb = (const float*)d_in[10];
    const float* Wout  = (const float*)d_in[11];
    const float* bout  = (const float*)d_in[12];
    float* out = (float*)d_out;

    static bool once = false;
    if (!once){
        cudaFuncSetAttribute(k_fused, cudaFuncAttributeMaxDynamicSharedMemorySize, SMEM_BYTES);
        once = true;
    }
    k_fused<<<NB, NT, SMEM_BYTES>>>(x, enc, hid, Wih, Whh, bih, bhh,
                                    Wattn, Wcomb, bcomb, Wout, bout, out);
}

// round 17
// speedup vs baseline: 1.2375x; 1.0164x over previous
#include <cuda_runtime.h>
#include <math.h>

#define B_ 32
#define S_ 128
#define V_ 32000
#define NB 148
#define NT 512
#define USTRIDE 36
#define SMU_FLOATS (1024*USTRIDE)
#define SMT_WARP   (2*16*34)
#define SMEM_BYTES ((SMU_FLOATS + 16*SMT_WARP)*4)   // 217088

typedef unsigned long long u64;

// ---------------- scratch ----------------
__device__ __align__(16) float g_gx[3072*32];         // x-gate accumulator [row][b]
__device__ __align__(16) float g_gh[3072*32];         // h-gate accumulator [row][b]
__device__ __align__(16) float g_v[32*1024];          // [b][e] (atomic-accumulated)
__device__ __align__(16) float g_ctx[1024*32];        // [e][b] (plain stores, owner-exclusive)
__device__ __align__(16) float g_outU[1024*32];       // [k][b] (init=bcomb, atomic-accumulated)
__device__ __align__(16) float g_logits[32*32000];    // [b][v]
__device__ float g_psb[32];                           // per-b exp-sum (atomic)

// ---------------- grid barrier ----------------
__device__ unsigned g_bar_cnt;
__device__ volatile unsigned g_bar_gen;

__device__ __forceinline__ void gsync(){
    __syncthreads();
    if (threadIdx.x == 0){
        unsigned target = g_bar_gen + 1u;
        __threadfence();
        if (atomicAdd(&g_bar_cnt, 1u) == NB - 1u){
            g_bar_cnt = 0u;
            __threadfence();
            g_bar_gen = target;
        } else {
            while ((int)(g_bar_gen - target) < 0) __nanosleep(64);
            __threadfence();
        }
    }
    __syncthreads();
}

// ---------------- f32x2 helpers ----------------
#define FMA2(acc,a,b) asm("fma.rn.f32x2 %0, %1, %2, %0;" : "+l"(acc) : "l"(a), "l"(b))
__device__ __forceinline__ u64 dup2(float w){ u64 r; asm("mov.b64 %0, {%1, %1};" : "=l"(r) : "f"(w)); return r; }
__device__ __forceinline__ u64 d2u(double d){ return (u64)__double_as_longlong(d); }
__device__ __forceinline__ void unpk(u64 v, float& a, float& b){ asm("mov.b64 {%0,%1}, %2;" : "=f"(a), "=f"(b) : "l"(v)); }
#define PREF_L2(p) asm volatile("prefetch.global.L2 [%0];" :: "l"(p))

__device__ __forceinline__ void rb_k(float w0, float w1, float w2, float w3,
                                     const float* Ub, u64 acc[16]){
    double2 ua = *(const double2*)(Ub);
    double2 ub = *(const double2*)(Ub + 4);
    u64 u0 = d2u(ua.x), u1 = d2u(ua.y), u2 = d2u(ub.x), u3 = d2u(ub.y);
    u64 d0 = dup2(w0), d1 = dup2(w1), d2 = dup2(w2), d3 = dup2(w3);
    FMA2(acc[0],  d0, u0); FMA2(acc[1],  d0, u1); FMA2(acc[2],  d0, u2); FMA2(acc[3],  d0, u3);
    FMA2(acc[4],  d1, u0); FMA2(acc[5],  d1, u1); FMA2(acc[6],  d1, u2); FMA2(acc[7],  d1, u3);
    FMA2(acc[8],  d2, u0); FMA2(acc[9],  d2, u1); FMA2(acc[10], d2, u2); FMA2(acc[11], d2, u3);
    FMA2(acc[12], d3, u0); FMA2(acc[13], d3, u1); FMA2(acc[14], d3, u2); FMA2(acc[15], d3, u3);
}

__device__ __forceinline__ void rb_j(float4 c0, float4 c1, float4 c2, float4 c3,
                                     const float* Ub, u64 acc[16]){
    rb_k(c0.x, c1.x, c2.x, c3.x, Ub,             acc);
    rb_k(c0.y, c1.y, c2.y, c3.y, Ub + USTRIDE,   acc);
    rb_k(c0.z, c1.z, c2.z, c3.z, Ub + 2*USTRIDE, acc);
    rb_k(c0.w, c1.w, c2.w, c3.w, Ub + 3*USTRIDE, acc);
}

__device__ __forceinline__ void rb_stage(float* st, const u64 acc[16], int rg, int bq, int par){
    float* s = st + par*(16*34);
    #pragma unroll
    for (int i = 0; i < 4; i++){
        #pragma unroll
        for (int p = 0; p < 4; p++){
            float lo, hi; unpk(acc[i*4+p], lo, hi);
            *(float2*)(s + (rg*4+i)*34 + bq*8 + 2*p) = make_float2(lo, hi);
        }
    }
    __syncwarp();
}

// comb GEMM block: 16 k-float4s per row group, rows i0..i0+127, RED to g_outU
__device__ __forceinline__ void comb_block(const float* __restrict__ Wcomb, const float* smU,
                                           float* stW, int i0, int kofs,
                                           int wid, int lane, int rg, int bq, int par){
    if (wid < 8){
        int urow0 = i0 + wid*16;
        int row0 = urow0 + rg*4;
        const float4* w0 = (const float4*)(Wcomb + (size_t)(row0+0)*2048 + kofs) + par;
        const float4* w1 = (const float4*)(Wcomb + (size_t)(row0+1)*2048 + kofs) + par;
        const float4* w2 = (const float4*)(Wcomb + (size_t)(row0+2)*2048 + kofs) + par;
        const float4* w3 = (const float4*)(Wcomb + (size_t)(row0+3)*2048 + kofs) + par;
        u64 acc[16];
        #pragma unroll
        for (int p = 0; p < 16; p++) acc[p] = 0;
        float4 a0 = w0[0], a1 = w1[0], a2 = w2[0], a3 = w3[0];
        #pragma unroll
        for (int j = 0; j < 16; j++){
            float4 c0 = a0, c1 = a1, c2 = a2, c3 = a3;
            if (j + 1 < 16){
                a0 = w0[2*(j+1)]; a1 = w1[2*(j+1)];
                a2 = w2[2*(j+1)]; a3 = w3[2*(j+1)];
            }
            rb_j(c0, c1, c2, c3, smU + ((2*j+par)*4)*USTRIDE + bq*8, acc);
        }
        rb_stage(stW, acc, rg, bq, par);
        #pragma unroll
        for (int r2 = 0; r2 < 16; r2++){
            float v = stW[r2*34 + lane] + stW[16*34 + r2*34 + lane];
            atomicAdd(&g_outU[(size_t)(urow0 + r2)*32 + lane], v);
        }
        __syncwarp();
    }
}

// split fp32 -> bf16 hi (truncate) pair + bf16 lo (rounded residual) pair
__device__ __forceinline__ void split2(float w0, float w1, unsigned& h2, unsigned& l2){
    unsigned u0 = __float_as_uint(w0), u1 = __float_as_uint(w1);
    h2 = __byte_perm(u0, u1, 0x7632);
    float l0 = w0 - __uint_as_float(u0 & 0xFFFF0000u);
    float l1 = w1 - __uint_as_float(u1 & 0xFFFF0000u);
    asm("cvt.rn.bf16x2.f32 %0, %1, %2;" : "=r"(l2) : "f"(l1), "f"(l0));
}

// m16n8k16 bf16 mma, f32 accumulate (base-arch instruction, sm_80+)
#define MMA16816(c, a, b0r, b1r) \
    asm volatile("mma.sync.aligned.m16n8k16.row.col.f32.bf16.bf16.f32 " \
        "{%0,%1,%2,%3}, {%4,%5,%6,%7}, {%8,%9}, {%0,%1,%2,%3};" \
        : "+f"((c)[0]), "+f"((c)[1]), "+f"((c)[2]), "+f"((c)[3]) \
        : "r"((a)[0]), "r"((a)[1]), "r"((a)[2]), "r"((a)[3]), "r"(b0r), "r"(b1r))

// ================= fused kernel =================
__global__ void __launch_bounds__(NT, 1) k_fused(
    const float* __restrict__ x, const float* __restrict__ enc,
    const float* __restrict__ hid,
    const float* __restrict__ Wih, const float* __restrict__ Whh,
    const float* __restrict__ bih, const float* __restrict__ bhh,
    const float* __restrict__ Wattn,
    const float* __restrict__ Wcomb, const float* __restrict__ bcomb,
    const float* __restrict__ Wout, const float* __restrict__ bout,
    float* __restrict__ out)
{
    extern __shared__ float smU[];
    float* smT = smU + SMU_FLOATS;
    const int bid = blockIdx.x, tid = threadIdx.x;
    const int wid = tid >> 5, lane = tid & 31;
    const int gtid = bid * NT + tid;
    const int gws = wid * NB + bid;     // block-balanced warp unit id
    const int rg  = lane >> 3;
    const int bq  = (lane >> 1) & 3;
    const int par = lane & 1;
    float* stW = smT + wid * SMT_WARP;

    // ---- Sinit: zero gate accumulators; prefetch GRU weights (24MB, fits L2) ----
    for (int u = gtid; u < 3072*32; u += NB*NT){ g_gx[u] = 0.0f; g_gh[u] = 0.0f; }
    for (int L = gtid; L < 98304; L += NB*NT){
        PREF_L2(Wih + (size_t)L*32);
        PREF_L2(Whh + (size_t)L*32);
    }
    gsync();

    // ---- S0: GRU gemm partials -> RED; idle blocks: enc prefetch + small inits ----
    if (bid < 128){
        int mat = bid >> 6, r = bid & 63;
        int kc = r >> 4, vb = r & 15;
        const float* W   = mat ? Whh : Wih;
        const float* src = mat ? hid : x;
        int k0 = kc * 256;
        for (int idx = tid; idx < 256*32; idx += NT){
            int b = idx >> 8, kk = idx & 255;
            smU[kk*USTRIDE + b] = src[b*1024 + k0 + kk];
        }
        __syncthreads();
        if (wid < 12){
            int urow0 = vb*192 + wid*16;
            int row0 = urow0 + rg*4;
            const float4* w0 = (const float4*)(W + (size_t)(row0+0)*1024 + k0) + par;
            const float4* w1 = (const float4*)(W + (size_t)(row0+1)*1024 + k0) + par;
            const float4* w2 = (const float4*)(W + (size_t)(row0+2)*1024 + k0) + par;
            const float4* w3 = (const float4*)(W + (size_t)(row0+3)*1024 + k0) + par;
            u64 acc[16];
            #pragma unroll
            for (int p = 0; p < 16; p++) acc[p] = 0;
            float4 a0 = w0[0], a1 = w1[0], a2 = w2[0], a3 = w3[0];
            for (int j = 0; j < 32; j++){
                float4 c0 = a0, c1 = a1, c2 = a2, c3 = a3;
                if (j + 1 < 32){
                    a0 = w0[2*(j+1)]; a1 = w1[2*(j+1)];
                    a2 = w2[2*(j+1)]; a3 = w3[2*(j+1)];
                }
                rb_j(c0, c1, c2, c3, smU + ((2*j+par)*4)*USTRIDE + bq*8, acc);
            }
            rb_stage(stW, acc, rg, bq, par);
            float* P = mat ? g_gh : g_gx;
            #pragma unroll
            for (int r2 = 0; r2 < 16; r2++){
                float v = stW[r2*34 + lane] + stW[16*34 + r2*34 + lane];
                atomicAdd(&P[(size_t)(urow0 + r2)*32 + lane], v);
            }
            __syncwarp();
        }
    } else {
        // blocks 128-147: enc prefetch (16MB) + g_v zero + g_outU=bcomb + g_psb zero
        int t0 = (bid - 128)*NT + tid;   // 0..10239
        for (int L = t0; L < 131072; L += 20*NT)
            PREF_L2(enc + (size_t)L*32);
        for (int u = t0; u < 32768; u += 20*NT){
            g_v[u] = 0.0f;
            g_outU[u] = bcomb[u >> 5];
        }
        if (t0 < 32) g_psb[t0] = 0.0f;
    }
    gsync();

    // ---- S2: v gemm (GRU activation fused into staging; all 512 threads, 2 k-halves) ----
    if (bid < 128){
        int kc = bid >> 2, e0 = (bid & 3) * 256;
        int k0 = kc * 32;
        for (int idx = tid; idx < 1024; idx += NT){
            int k = idx >> 5, b = idx & 31;
            int h = k0 + k;
            float xr = g_gx[(size_t)h*32+b]          + bih[h];
            float xz = g_gx[(size_t)(1024+h)*32+b]   + bih[1024+h];
            float xn = g_gx[(size_t)(2048+h)*32+b]   + bih[2048+h];
            float hr = g_gh[(size_t)h*32+b]          + bhh[h];
            float hz = g_gh[(size_t)(1024+h)*32+b]   + bhh[1024+h];
            float hn = g_gh[(size_t)(2048+h)*32+b]   + bhh[2048+h];
            float rr = 1.0f/(1.0f+__expf(-(xr+hr)));
            float zz = 1.0f/(1.0f+__expf(-(xz+hz)));
            float nn = tanhf(xn + rr*hn);
            smU[k*USTRIDE + b] = (1.0f-zz)*nn + zz*hid[b*1024+h];
        }
        __syncthreads();
        {
            int kh = tid >> 8;               // 0/1: k-half
            int e = e0 + (tid & 255);
            int kb = kh * 16;
            const float* wp = Wattn + (size_t)(k0 + kb)*2048 + 1024 + e;
            u64 acc[16];
            #pragma unroll
            for (int p = 0; p < 16; p++) acc[p] = 0;
            #pragma unroll 8
            for (int k = 0; k < 16; k++){
                u64 wd = dup2(wp[(size_t)k*2048]);
                #pragma unroll
                for (int p = 0; p < 16; p += 2){
                    double2 u2 = *(const double2*)(smU + (kb + k)*USTRIDE + 2*p);
                    FMA2(acc[p],   wd, d2u(u2.x));
                    FMA2(acc[p+1], wd, d2u(u2.y));
                }
            }
            #pragma unroll
            for (int p = 0; p < 16; p++){
                float lo, hi; unpk(acc[p], lo, hi);
                atomicAdd(&g_v[(size_t)(2*p  )*1024 + e], lo);
                atomicAdd(&g_v[(size_t)(2*p+1)*1024 + e], hi);
            }
        }
    } else {
        // blocks 128-147: prefetch Wcomb (8MB)
        for (int L = (bid - 128)*NT + tid; L < 65536; L += 20*NT)
            PREF_L2(Wcomb + (size_t)L*32);
    }
    gsync();

    // ---- S456: blocks 0-31: scores->softmax->context; 32-95: comb x-half; 96-147: Wout head prefetch ----
    if (bid < 32){
        int b = bid;
        #pragma unroll
        for (int q = 0; q < 8; q++){
            int s = wid*8 + q;
            const float4* ep = (const float4*)(enc + (size_t)(s*32+b)*1024);
            const float4* vp = (const float4*)(g_v + b*1024);
            float a = 0.0f;
            #pragma unroll
            for (int i = 0; i < 8; i++){
                float4 e4 = ep[i*32 + lane];
                float4 v4 = vp[i*32 + lane];
                a += e4.x*v4.x + e4.y*v4.y + e4.z*v4.z + e4.w*v4.w;
            }
            #pragma unroll
            for (int o = 16; o; o >>= 1) a += __shfl_xor_sync(0xFFFFFFFFu, a, o);
            if (lane == 0) smU[s] = a;
        }
        __syncthreads();
        if (wid == 0){
            float v0 = smU[lane], v1 = smU[32+lane], v2 = smU[64+lane], v3 = smU[96+lane];
            float m = fmaxf(fmaxf(v0,v1), fmaxf(v2,v3));
            #pragma unroll
            for (int o = 16; o; o >>= 1) m = fmaxf(m, __shfl_xor_sync(0xFFFFFFFFu, m, o));
            float e0 = expf(v0-m), e1 = expf(v1-m), e2 = expf(v2-m), e3 = expf(v3-m);
            float s = e0+e1+e2+e3;
            #pragma unroll
            for (int o = 16; o; o >>= 1) s += __shfl_xor_sync(0xFFFFFFFFu, s, o);
            float inv = 1.0f / s;
            float w0 = e0*inv, w1 = e1*inv, w2 = e2*inv, w3 = e3*inv;
            smU[128 + lane]      = w0;  out[(size_t)B_*V_ + b*128 + lane]      = w0;
            smU[128 + 32 + lane] = w1;  out[(size_t)B_*V_ + b*128 + 32 + lane] = w1;
            smU[128 + 64 + lane] = w2;  out[(size_t)B_*V_ + b*128 + 64 + lane] = w2;
            smU[128 + 96 + lane] = w3;  out[(size_t)B_*V_ + b*128 + 96 + lane] = w3;
        }
        __syncthreads();
        {
            const float* ws = smU + 128;
            int e1i = tid, e2i = tid + 512;
            const float* ep = enc + (size_t)b*1024;
            float a1 = 0.0f, a2 = 0.0f;
            #pragma unroll 16
            for (int s = 0; s < 128; s++){
                float w = ws[s];
                a1 += w * ep[(size_t)s*32768 + e1i];
                a2 += w * ep[(size_t)s*32768 + e2i];
            }
            g_ctx[e1i*32 + b] = a1;
            g_ctx[e2i*32 + b] = a2;
        }
    } else if (bid < 96){
        int b2 = bid - 32;
        int kc = b2 >> 3, rc = b2 & 7;
        int k0 = kc * 128;
        for (int idx = tid; idx < 128*32; idx += NT){
            int b = idx >> 7, kk = idx & 127;
            smU[kk*USTRIDE + b] = x[b*1024 + k0 + kk];
        }
        __syncthreads();
        comb_block(Wcomb, smU, stW, rc*128, k0, wid, lane, rg, bq, par);
    } else {
        // blocks 96-147 (26624 threads): prefetch Wout head: lines 0-4 of every row (20MB)
        int t0 = (bid - 96)*NT + tid;
        for (int L = t0; L < 160000; L += 52*NT){
            int row = L / 5, c = L % 5;
            PREF_L2(Wout + (size_t)row*1024 + c*32);
        }
    }
    gsync();

    // ---- S7: comb ctx-half GEMM (blocks 0-63); 64-147: Wout head prefetch (lines 5-9) ----
    if (bid < 64){
        int kc8 = bid >> 3, rc = bid & 7;
        int k0c = kc8 * 128;
        for (int idx = tid; idx < 128*32; idx += NT){
            int kk = idx >> 5, b = idx & 31;
            smU[kk*USTRIDE + b] = g_ctx[(k0c + kk)*32 + b];
        }
        __syncthreads();
        comb_block(Wcomb, smU, stW, rc*128, 1024 + k0c, wid, lane, rg, bq, par);
    } else {
        // blocks 64-147 (43008 threads): prefetch Wout lines 5-9 of every row (20MB)
        int t0 = (bid - 64)*NT + tid;
        for (int L = t0; L < 160000; L += 84*NT){
            int row = L / 5, c = 5 + L % 5;
            PREF_L2(Wout + (size_t)row*1024 + c*32);
        }
    }
    gsync();

    // ---- S9: W_out gemm via mma.sync + fused exp-sum epilogue ----
    {
        uint4* Bs = (uint4*)smU;   // [ks*4 + g][lane] (128KB)
        for (int idx = tid; idx < 4096; idx += NT){
            int l = idx & 31, rest = idx >> 5;
            int ks = rest >> 1, reg = rest & 1;
            int kb = ks*16 + (l&3)*2 + reg*8;
            int nb = l >> 2;
            uint4 hv, lv; unsigned h, lo;
            split2(g_outU[kb*32 + nb],      g_outU[(kb+1)*32 + nb],      h, lo); hv.x = h; lv.x = lo;
            split2(g_outU[kb*32 + nb + 8],  g_outU[(kb+1)*32 + nb + 8],  h, lo); hv.y = h; lv.y = lo;
            split2(g_outU[kb*32 + nb + 16], g_outU[(kb+1)*32 + nb + 16], h, lo); hv.z = h; lv.z = lo;
            split2(g_outU[kb*32 + nb + 24], g_outU[(kb+1)*32 + nb + 24], h, lo); hv.w = h; lv.w = lo;
            Bs[(ks*4 + reg)*32 + l]     = hv;
            Bs[(ks*4 + 2 + reg)*32 + l] = lv;
        }
        if (tid < 32) smT[tid] = 0.0f;     // per-block exp-sum accumulator
        __syncthreads();

        for (int wu = gws; wu < 2000; wu += NB*16){
            int v0 = wu * 16;
            int r = lane >> 2, c = (lane & 3) * 2;
            const float* p0 = Wout + (size_t)(v0 + r)*1024 + c;
            const float* p1 = Wout + (size_t)(v0 + r + 8)*1024 + c;
            float acc[4][4];
            #pragma unroll
            for (int nt = 0; nt < 4; nt++)
                #pragma unroll
                for (int i = 0; i < 4; i++) acc[nt][i] = 0.0f;

            float2 fA[4][4];                 // depth-4 prefetch ring
            #pragma unroll
            for (int s = 0; s < 4; s++){
                const float* q0 = p0 + s*16;
                const float* q1 = p1 + s*16;
                fA[s][0] = *(const float2*)(q0);
                fA[s][1] = *(const float2*)(q1);
                fA[s][2] = *(const float2*)(q0 + 8);
                fA[s][3] = *(const float2*)(q1 + 8);
            }

            #pragma unroll 4
            for (int ks = 0; ks < 64; ks++){
                int sl = ks & 3;
                float2 g0 = fA[sl][0], g1 = fA[sl][1], g2 = fA[sl][2], g3 = fA[sl][3];
                if (ks + 4 < 64){
                    const float* q0 = p0 + (ks+4)*16;
                    const float* q1 = p1 + (ks+4)*16;
                    fA[sl][0] = *(const float2*)(q0);
                    fA[sl][1] = *(const float2*)(q1);
                    fA[sl][2] = *(const float2*)(q0 + 8);
                    fA[sl][3] = *(const float2*)(q1 + 8);
                }
                unsigned ah[4], al[4];
                split2(g0.x, g0.y, ah[0], al[0]);
                split2(g1.x, g1.y, ah[1], al[1]);
                split2(g2.x, g2.y, ah[2], al[2]);
                split2(g3.x, g3.y, ah[3], al[3]);
                uint4* Bsl = (uint4*)smU;
                {
                    uint4 bh0 = Bsl[(ks*4+0)*32 + lane];
                    uint4 bh1 = Bsl[(ks*4+1)*32 + lane];
                    MMA16816(acc[0], ah, bh0.x, bh1.x);
                    MMA16816(acc[0], al, bh0.x, bh1.x);
                    MMA16816(acc[1], ah, bh0.y, bh1.y);
                    MMA16816(acc[1], al, bh0.y, bh1.y);
                    MMA16816(acc[2], ah, bh0.z, bh1.z);
                    MMA16816(acc[2], al, bh0.z, bh1.z);
                    MMA16816(acc[3], ah, bh0.w, bh1.w);
                    MMA16816(acc[3], al, bh0.w, bh1.w);
                }
                {
                    uint4 bl0 = Bsl[(ks*4+2)*32 + lane];
                    uint4 bl1 = Bsl[(ks*4+3)*32 + lane];
                    MMA16816(acc[0], ah, bl0.x, bl1.x);
                    MMA16816(acc[1], ah, bl0.y, bl1.y);
                    MMA16816(acc[2], ah, bl0.z, bl1.z);
                    MMA16816(acc[3], ah, bl0.w, bl1.w);
                }
            }

            float bb0 = bout[v0 + r], bb1 = bout[v0 + r + 8];
            float pb0[4], pb1[4];
            #pragma unroll
            for (int nt = 0; nt < 4; nt++){
                int jg = nt*8 + c;
                float x0 = acc[nt][0] + bb0;
                float x1 = acc[nt][1] + bb0;
                float x2 = acc[nt][2] + bb1;
                float x3 = acc[nt][3] + bb1;
                g_logits[(size_t)jg*V_     + v0 + r]     = x0;
                g_logits[(size_t)(jg+1)*V_ + v0 + r]     = x1;
                g_logits[(size_t)jg*V_     + v0 + r + 8] = x2;
                g_logits[(size_t)(jg+1)*V_ + v0 + r + 8] = x3;
                pb0[nt] = __expf(x0) + __expf(x2);   // b = jg
                pb1[nt] = __expf(x1) + __expf(x3);   // b = jg+1
            }
            #pragma unroll
            for (int o = 4; o <= 16; o <<= 1){
                #pragma unroll
                for (int nt = 0; nt < 4; nt++){
                    pb0[nt] += __shfl_xor_sync(0xFFFFFFFFu, pb0[nt], o);
                    pb1[nt] += __shfl_xor_sync(0xFFFFFFFFu, pb1[nt], o);
                }
            }
            if (lane < 4){
                #pragma unroll
                for (int nt = 0; nt < 4; nt++){
                    atomicAdd(&smT[nt*8 + c],     pb0[nt]);
                    atomicAdd(&smT[nt*8 + c + 1], pb1[nt]);
                }
            }
        }
        __syncthreads();
        if (tid < 32) atomicAdd(&g_psb[tid], smT[tid]);
    }
    gsync();

    // ---- S11+S12: off = log(sum) + final write ----
    if (tid < 32) smU[tid] = logf(g_psb[tid]);
    __syncthreads();
    for (int u = gtid; u < 256000; u += NB*NT){
        int b = u / 8000, r = u - b*8000;
        float4 a = ((const float4*)(g_logits + (size_t)b*V_))[r];
        float off = smU[b];
        ((float4*)(out + (size_t)b*V_))[r] =
            make_float4(a.x-off, a.y-off, a.z-off, a.w-off);
    }
}

// ---------------- launch ----------------
extern "C" void kernel_launch(void* const* d_in, const int* in_sizes, int n_in,
                              void* d_out, int out_size)
{
    const float* x     = (const float*)d_in[0];
    const float* enc   = (const float*)d_in[1];
    const float* hid   = (const float*)d_in[2];
    const float* Wih   = (const float*)d_in[3];
    const float* Whh   = (const float*)d_in[4];
    const float* bih   = (const float*)d_in[5];
    const float* bhh   = (const float*)d_in[6];
    const float* Wattn = (const float*)d_in[7];
    // d_in[8] = b_attn: softmax-invariant, unused
    const float* Wcomb = (const float*)d_in[9];
    const float* bcomb = (const float*)d_in[10];
    const float* Wout  = (const float*)d_in[11];
    const float* bout  = (const float*)d_in[12];
    float* out = (float*)d_out;

    static bool once = false;
    if (!once){
        cudaFuncSetAttribute(k_fused, cudaFuncAttributeMaxDynamicSharedMemorySize, SMEM_BYTES);
        once = true;
    }
    k_fused<<<NB, NT, SMEM_BYTES>>>(x, enc, hid, Wih, Whh, bih, bhh,
                                    Wattn, Wcomb, bcomb, Wout, bout, out);
}